// round 1
// baseline (speedup 1.0000x reference)
#include <cuda_runtime.h>
#include <math.h>
#include <stdint.h>

#define T_TOK 2048
#define HID   2048
#define NH    16
#define HD    128
#define NQG   2064      // H*D + H
#define WIN   128

// ---------------- scratch (static device globals; no runtime allocation) ----
__device__ float d_qg[T_TOK * NQG];     // X @ Wq  (q cols 0..2047, gate cols 2048..2063)
__device__ float d_kbuf[T_TOK * HID];   // X @ Wk  -> normed+roped in place
__device__ float d_vbuf[T_TOK * HID];   // X @ Wv
__device__ float d_blend[T_TOK * HID];  // gated attention output

// ---------------- fp32 SGEMM: C[M,N] = A[M,K] @ B[K,N], row-major ----------
// 128x128 tile, BK=8, 256 threads, 8x8 per-thread micro-tile.
__global__ __launch_bounds__(256) void sgemm_kernel(
    const float* __restrict__ A, const float* __restrict__ B,
    float* __restrict__ C, int M, int N, int K)
{
    __shared__ float As[8][128];   // transposed A tile: As[k][m]
    __shared__ float Bs[8][128];

    const int tid  = threadIdx.x;
    const int bm   = blockIdx.y * 128;
    const int bn   = blockIdx.x * 128;
    const int rowA = tid >> 1,  colA = (tid & 1) * 4;   // A loader: 128 rows x 8 k
    const int rowB = tid >> 5,  colB = (tid & 31) * 4;  // B loader: 8 k x 128 cols
    const int tr   = (tid >> 4) * 8;
    const int tc   = (tid & 15) * 8;

    float acc[8][8] = {};

    for (int k0 = 0; k0 < K; k0 += 8) {
        float4 a4 = *reinterpret_cast<const float4*>(
            A + (size_t)(bm + rowA) * K + k0 + colA);
        float4 b4 = make_float4(0.f, 0.f, 0.f, 0.f);
        if (bn + colB < N)   // N % 4 == 0 -> float4 fully in or out
            b4 = *reinterpret_cast<const float4*>(
                B + (size_t)(k0 + rowB) * N + bn + colB);

        __syncthreads();
        As[colA + 0][rowA] = a4.x;
        As[colA + 1][rowA] = a4.y;
        As[colA + 2][rowA] = a4.z;
        As[colA + 3][rowA] = a4.w;
        *reinterpret_cast<float4*>(&Bs[rowB][colB]) = b4;
        __syncthreads();

        #pragma unroll
        for (int kk = 0; kk < 8; kk++) {
            float ar[8], br[8];
            *reinterpret_cast<float4*>(ar)     = *reinterpret_cast<const float4*>(&As[kk][tr]);
            *reinterpret_cast<float4*>(ar + 4) = *reinterpret_cast<const float4*>(&As[kk][tr + 4]);
            *reinterpret_cast<float4*>(br)     = *reinterpret_cast<const float4*>(&Bs[kk][tc]);
            *reinterpret_cast<float4*>(br + 4) = *reinterpret_cast<const float4*>(&Bs[kk][tc + 4]);
            #pragma unroll
            for (int i = 0; i < 8; i++)
                #pragma unroll
                for (int j = 0; j < 8; j++)
                    acc[i][j] = fmaf(ar[i], br[j], acc[i][j]);
        }
    }

    #pragma unroll
    for (int i = 0; i < 8; i++) {
        float* crow = C + (size_t)(bm + tr + i) * N + bn;
        #pragma unroll
        for (int j = 0; j < 8; j += 4) {
            if (bn + tc + j < N)
                *reinterpret_cast<float4*>(crow + tc + j) =
                    make_float4(acc[i][j], acc[i][j + 1], acc[i][j + 2], acc[i][j + 3]);
        }
    }
}

// ---------------- fused RMSNorm (full 2048-dim row) + NeoX RoPE ------------
__global__ __launch_bounds__(256) void norm_rope_kernel(
    float* __restrict__ qg, float* __restrict__ kb,
    const float* __restrict__ qw, const float* __restrict__ kw,
    const int* __restrict__ positions)
{
    const int t   = blockIdx.x;
    const int tid = threadIdx.x;
    __shared__ float red[256];
    __shared__ float cs[64], sn[64];
    __shared__ float rq_s, rk_s;

    float* qrow = qg + (size_t)t * NQG;
    float* krow = kb + (size_t)t * HID;

    float sq = 0.f, sk = 0.f;
    for (int i = tid; i < HID; i += 256) {
        float a = qrow[i]; sq = fmaf(a, a, sq);
        float b = krow[i]; sk = fmaf(b, b, sk);
    }
    red[tid] = sq; __syncthreads();
    for (int s = 128; s > 0; s >>= 1) { if (tid < s) red[tid] += red[tid + s]; __syncthreads(); }
    if (tid == 0) rq_s = rsqrtf(red[0] * (1.f / (float)HID) + 1e-6f);
    __syncthreads();
    red[tid] = sk; __syncthreads();
    for (int s = 128; s > 0; s >>= 1) { if (tid < s) red[tid] += red[tid + s]; __syncthreads(); }
    if (tid == 0) rk_s = rsqrtf(red[0] * (1.f / (float)HID) + 1e-6f);

    if (tid < 64) {
        // inv_freq[j] = 500000^(-j/64), angle in double for accuracy
        double invf = exp(-(double)tid * (log(500000.0) / 64.0));
        double ang  = (double)positions[t] * invf;
        double sd, cd;
        sincos(ang, &sd, &cd);
        cs[tid] = (float)cd;
        sn[tid] = (float)sd;
    }
    __syncthreads();

    const float rq = rq_s, rk = rk_s;
    for (int pid = tid; pid < NH * 64; pid += 256) {
        int hh = pid >> 6, j = pid & 63;
        int i1 = hh * HD + j, i2 = i1 + 64;
        float c = cs[j], s = sn[j];
        float x1 = qrow[i1] * rq * qw[i1];
        float x2 = qrow[i2] * rq * qw[i2];
        qrow[i1] = x1 * c - x2 * s;
        qrow[i2] = x2 * c + x1 * s;
        float y1 = krow[i1] * rk * kw[i1];
        float y2 = krow[i2] * rk * kw[i2];
        krow[i1] = y1 * c - y2 * s;
        krow[i2] = y2 * c + y1 * s;
    }
}

// ---------------- dual (global causal + local window) flash attention -------
// grid (64, 16): 32-query block per CTA per head. 128 threads = 4 warps,
// each warp owns 8 query rows; lane = key within the 32-key tile.
// One QK^T evaluation feeds BOTH online softmaxes; local accumulator is
// only touched on the <=5 key tiles that can intersect the 128 window.
__global__ __launch_bounds__(128) void attn_kernel(
    const float* __restrict__ qg, const float* __restrict__ kb,
    const float* __restrict__ vb, float* __restrict__ outp,
    const int* __restrict__ positions)
{
    extern __shared__ float smem[];
    float* Qs = smem;                 // 32 x 128 (broadcast reads: no pad)
    float* Ks = Qs + 32 * 128;        // 32 x 132 (padded for LDS.128 by lane)
    float* Vs = Ks + 32 * 132;        // 32 x 128 (column reads: bank-clean)
    int*  qpos = (int*)(Vs + 32 * 128);
    int*  kpos = qpos + 32;

    const int qb   = (int)gridDim.x - 1 - (int)blockIdx.x;  // heavy blocks first
    const int h    = blockIdx.y;
    const int tid  = threadIdx.x;
    const int warp = tid >> 5, lane = tid & 31;
    const int r0   = warp * 8;
    const float scale = 0.08838834764831843f;  // 128^-0.5

    for (int i = tid; i < 32 * 128; i += 128) {
        int r = i >> 7, c = i & 127;
        Qs[r * 128 + c] = qg[(size_t)(qb * 32 + r) * NQG + h * HD + c] * scale;
    }
    if (tid < 32) qpos[tid] = positions[qb * 32 + tid];

    float accg[8][4], accl[8][4], mg[8], lg[8], ml[8], ll[8];
    #pragma unroll
    for (int r = 0; r < 8; r++) {
        mg[r] = -1e30f; lg[r] = 0.f; ml[r] = -1e30f; ll[r] = 0.f;
        #pragma unroll
        for (int c = 0; c < 4; c++) { accg[r][c] = 0.f; accl[r][c] = 0.f; }
    }

    for (int kt = 0; kt <= qb; kt++) {
        __syncthreads();
        for (int i = tid; i < 32 * 128; i += 128) {
            int r = i >> 7, c = i & 127;
            size_t g = (size_t)(kt * 32 + r) * HID + h * HD + c;
            Ks[r * 132 + c] = kb[g];
            Vs[r * 128 + c] = vb[g];
        }
        if (tid < 32) kpos[tid] = positions[kt * 32 + tid];
        __syncthreads();

        // scores: this lane's key vs warp's 8 query rows
        float s[8];
        #pragma unroll
        for (int r = 0; r < 8; r++) s[r] = 0.f;
        for (int c4 = 0; c4 < 128; c4 += 4) {
            float4 kv = *reinterpret_cast<const float4*>(&Ks[lane * 132 + c4]);
            #pragma unroll
            for (int r = 0; r < 8; r++) {
                float4 qv = *reinterpret_cast<const float4*>(&Qs[(r0 + r) * 128 + c4]);
                s[r] += qv.x * kv.x + qv.y * kv.y + qv.z * kv.z + qv.w * kv.w;
            }
        }

        const int  kp = kpos[lane];
        const bool local_tile = (kt >= qb - 4);  // tiles that can touch the window
        float pg[8], pl[8];
        #pragma unroll
        for (int r = 0; r < 8; r++) {
            const int  qp     = qpos[r0 + r];
            const bool causal = (qp >= kp);
            const bool loc    = causal && (qp - kp < WIN);

            // ---- global online softmax
            float sg = causal ? s[r] : -1e30f;
            float tmax = sg;
            #pragma unroll
            for (int o = 16; o > 0; o >>= 1)
                tmax = fmaxf(tmax, __shfl_xor_sync(0xffffffffu, tmax, o));
            float mnew  = fmaxf(mg[r], tmax);
            float alpha = __expf(mg[r] - mnew);
            float p     = causal ? __expf(s[r] - mnew) : 0.f;
            float psum  = p;
            #pragma unroll
            for (int o = 16; o > 0; o >>= 1)
                psum += __shfl_xor_sync(0xffffffffu, psum, o);
            lg[r] = lg[r] * alpha + psum;
            mg[r] = mnew;
            #pragma unroll
            for (int c = 0; c < 4; c++) accg[r][c] *= alpha;
            pg[r] = p;

            // ---- local online softmax (window tiles only)
            if (local_tile) {
                float sl = loc ? s[r] : -1e30f;
                float tml = sl;
                #pragma unroll
                for (int o = 16; o > 0; o >>= 1)
                    tml = fmaxf(tml, __shfl_xor_sync(0xffffffffu, tml, o));
                float mnl = fmaxf(ml[r], tml);
                float al  = __expf(ml[r] - mnl);
                float q   = loc ? __expf(s[r] - mnl) : 0.f;
                float qs  = q;
                #pragma unroll
                for (int o = 16; o > 0; o >>= 1)
                    qs += __shfl_xor_sync(0xffffffffu, qs, o);
                ll[r] = ll[r] * al + qs;
                ml[r] = mnl;
                #pragma unroll
                for (int c = 0; c < 4; c++) accl[r][c] *= al;
                pl[r] = q;
            }
        }

        // ---- P @ V (lane owns output cols lane, lane+32, lane+64, lane+96)
        #pragma unroll 4
        for (int key = 0; key < 32; key++) {
            float v0 = Vs[key * 128 + lane];
            float v1 = Vs[key * 128 + lane + 32];
            float v2 = Vs[key * 128 + lane + 64];
            float v3 = Vs[key * 128 + lane + 96];
            #pragma unroll
            for (int r = 0; r < 8; r++) {
                float w = __shfl_sync(0xffffffffu, pg[r], key);
                accg[r][0] = fmaf(w, v0, accg[r][0]);
                accg[r][1] = fmaf(w, v1, accg[r][1]);
                accg[r][2] = fmaf(w, v2, accg[r][2]);
                accg[r][3] = fmaf(w, v3, accg[r][3]);
            }
            if (local_tile) {
                #pragma unroll
                for (int r = 0; r < 8; r++) {
                    float w = __shfl_sync(0xffffffffu, pl[r], key);
                    accl[r][0] = fmaf(w, v0, accl[r][0]);
                    accl[r][1] = fmaf(w, v1, accl[r][1]);
                    accl[r][2] = fmaf(w, v2, accl[r][2]);
                    accl[r][3] = fmaf(w, v3, accl[r][3]);
                }
            }
        }
    }

    // ---- epilogue: hard gate picks global vs local, normalize, store
    #pragma unroll
    for (int r = 0; r < 8; r++) {
        int t = qb * 32 + r0 + r;
        float g = qg[(size_t)t * NQG + NH * HD + h];   // pre-sigmoid gate logit
        bool useg = (g > 0.f);                          // sigmoid(g) > 0.5
        float inv = 1.f / (useg ? lg[r] : ll[r]);
        #pragma unroll
        for (int c = 0; c < 4; c++) {
            float val = (useg ? accg[r][c] : accl[r][c]) * inv;
            outp[(size_t)t * HID + h * HD + lane + c * 32] = val;
        }
    }
}

// ---------------------------------------------------------------------------
extern "C" void kernel_launch(void* const* d_in, const int* in_sizes, int n_in,
                              void* d_out, int out_size)
{
    const float* X   = (const float*)d_in[0];
    const int*   pos = (const int*)  d_in[1];
    const float* Wq  = (const float*)d_in[2];
    const float* Wk  = (const float*)d_in[3];
    const float* Wv  = (const float*)d_in[4];
    const float* Wo  = (const float*)d_in[5];
    const float* qw  = (const float*)d_in[6];
    const float* kw  = (const float*)d_in[7];
    float* out = (float*)d_out;

    float *qg, *kb, *vb, *bl;
    cudaGetSymbolAddress((void**)&qg, d_qg);
    cudaGetSymbolAddress((void**)&kb, d_kbuf);
    cudaGetSymbolAddress((void**)&vb, d_vbuf);
    cudaGetSymbolAddress((void**)&bl, d_blend);

    const int attn_smem = (32 * 128 + 32 * 132 + 32 * 128) * 4 + 64 * 4;  // 49920 B
    cudaFuncSetAttribute(attn_kernel, cudaFuncAttributeMaxDynamicSharedMemorySize,
                         attn_smem);

    dim3 blk(256);
    dim3 gq((NQG + 127) / 128, T_TOK / 128);   // 17 x 16
    dim3 gs(HID / 128, T_TOK / 128);           // 16 x 16

    sgemm_kernel<<<gq, blk>>>(X, Wq, qg, T_TOK, NQG, HID);
    sgemm_kernel<<<gs, blk>>>(X, Wk, kb, T_TOK, HID, HID);
    sgemm_kernel<<<gs, blk>>>(X, Wv, vb, T_TOK, HID, HID);

    norm_rope_kernel<<<T_TOK, 256>>>(qg, kb, qw, kw, pos);

    dim3 ga(T_TOK / 32, NH);                   // 64 x 16
    attn_kernel<<<ga, 128, attn_smem>>>(qg, kb, vb, bl, pos);

    sgemm_kernel<<<gs, blk>>>(bl, Wo, out, T_TOK, HID, HID);
}

// round 4
// speedup vs baseline: 1.2356x; 1.2356x over previous
#include <cuda_runtime.h>
#include <cuda_bf16.h>
#include <math.h>
#include <stdint.h>

#define T_TOK 2048
#define HID   2048
#define NH    16
#define HD    128
#define NQG   2064      // H*D + H
#define WIN   128

// ---------------- scratch (static device globals; no runtime allocation) ----
__device__ float d_qg[T_TOK * NQG];     // X @ Wq  (q cols 0..2047, gate cols 2048..2063)
__device__ float d_kbuf[T_TOK * HID];   // X @ Wk  -> normed+roped in place
__device__ float d_vbuf[T_TOK * HID];   // X @ Wv
__device__ float d_blend[T_TOK * HID];  // gated attention output

// ============================================================================
// bf16x3 tensor-core GEMM:  C[M,N] = A[M,K] @ B[K,N]  (fp32 in/out)
// Each fp32 split into bf16 hi+lo; D += Ah*Bh + Ah*Bl + Al*Bh (fp32 accum).
// 128x128 CTA tile, BK=16, 256 threads (8 warps, 32x64 warp tiles),
// double-buffered smem, ldmatrix + mma.sync.m16n8k16.
// M, N assumed multiples of 128 (M=N=2048 here); lda = K.
// ============================================================================

__device__ __forceinline__ uint32_t smem_u32(const void* p) {
    return (uint32_t)__cvta_generic_to_shared(p);
}

__device__ __forceinline__ void ldsm_x4(uint32_t* r, uint32_t addr) {
    asm volatile("ldmatrix.sync.aligned.m8n8.x4.shared.b16 {%0,%1,%2,%3}, [%4];\n"
        : "=r"(r[0]), "=r"(r[1]), "=r"(r[2]), "=r"(r[3]) : "r"(addr));
}

__device__ __forceinline__ void mma16816(float* d, const uint32_t* a, const uint32_t* b) {
    asm volatile(
        "mma.sync.aligned.m16n8k16.row.col.f32.bf16.bf16.f32 "
        "{%0,%1,%2,%3}, {%4,%5,%6,%7}, {%8,%9}, {%0,%1,%2,%3};\n"
        : "+f"(d[0]), "+f"(d[1]), "+f"(d[2]), "+f"(d[3])
        : "r"(a[0]), "r"(a[1]), "r"(a[2]), "r"(a[3]), "r"(b[0]), "r"(b[1]));
}

__device__ __forceinline__ void cvt_store8(__nv_bfloat16* hi, __nv_bfloat16* lo,
                                           const float* v) {
    union { __nv_bfloat16 b[8]; uint4 u; } ph, pl;
    #pragma unroll
    for (int j = 0; j < 8; j++) {
        __nv_bfloat16 h = __float2bfloat16(v[j]);
        ph.b[j] = h;
        pl.b[j] = __float2bfloat16(v[j] - __bfloat162float(h));
    }
    *(uint4*)hi = ph.u;
    *(uint4*)lo = pl.u;
}

#define SSTR 24                     // bf16 row stride (16 + 8 pad) -> 48B, cf-free
#define STAGE_ELEMS (4 * 128 * SSTR)
#define GEMM_SMEM (2 * STAGE_ELEMS * 2)   // bytes = 49152

__global__ __launch_bounds__(256) void mma_gemm(
    const float* __restrict__ A, const float* __restrict__ B,
    float* __restrict__ C, int K, int ldb, int ldc)
{
    extern __shared__ char smraw[];
    __nv_bfloat16* sm = (__nv_bfloat16*)smraw;

    const int tid  = threadIdx.x;
    const int warp = tid >> 5, lane = tid & 31;
    const int bm   = blockIdx.y * 128, bn = blockIdx.x * 128;

    const int A_LO = 128 * SSTR;
    const int B_HI = 2 * 128 * SSTR;
    const int B_LO = 3 * 128 * SSTR;

    // loader indices
    const int arow = tid >> 1;            // 0..127
    const int akq  = (tid & 1) * 8;       // 0 / 8
    const int bnn  = tid & 127;           // n within tile
    const int bkh  = (tid >> 7) * 8;      // k half 0 / 8

    // compute indices
    const int wm = (warp & 3) * 32;
    const int wn = (warp >> 2) * 64;
    const int g  = lane >> 2, tg = lane & 3;

    float acc[2][8][4];
    #pragma unroll
    for (int mt = 0; mt < 2; mt++)
        #pragma unroll
        for (int nt = 0; nt < 8; nt++)
            #pragma unroll
            for (int i = 0; i < 4; i++) acc[mt][nt][i] = 0.f;

    float av[8], bv[8];

    // ---- initial tile load (k0 = 0)
    {
        const float* ap = A + (size_t)(bm + arow) * K + akq;
        float4 x = *(const float4*)ap;
        float4 y = *(const float4*)(ap + 4);
        av[0]=x.x; av[1]=x.y; av[2]=x.z; av[3]=x.w;
        av[4]=y.x; av[5]=y.y; av[6]=y.z; av[7]=y.w;
        const float* bp = B + (size_t)bkh * ldb + bn + bnn;
        #pragma unroll
        for (int j = 0; j < 8; j++) bv[j] = bp[(size_t)j * ldb];
    }
    cvt_store8(sm + arow * SSTR + akq, sm + A_LO + arow * SSTR + akq, av);
    cvt_store8(sm + B_HI + bnn * SSTR + bkh, sm + B_LO + bnn * SSTR + bkh, bv);
    __syncthreads();

    const int KT = K >> 4;   // K/16
    for (int kt = 0; kt < KT; kt++) {
        const int cur = (kt & 1) ? STAGE_ELEMS : 0;

        // prefetch next tile into registers
        if (kt + 1 < KT) {
            const int k0 = (kt + 1) << 4;
            const float* ap = A + (size_t)(bm + arow) * K + k0 + akq;
            float4 x = *(const float4*)ap;
            float4 y = *(const float4*)(ap + 4);
            av[0]=x.x; av[1]=x.y; av[2]=x.z; av[3]=x.w;
            av[4]=y.x; av[5]=y.y; av[6]=y.z; av[7]=y.w;
            const float* bp = B + (size_t)(k0 + bkh) * ldb + bn + bnn;
            #pragma unroll
            for (int j = 0; j < 8; j++) bv[j] = bp[(size_t)j * ldb];
        }

        const __nv_bfloat16* Ah = sm + cur;
        const __nv_bfloat16* Al = Ah + A_LO;
        const __nv_bfloat16* Bh = sm + cur + B_HI;
        const __nv_bfloat16* Bl = sm + cur + B_LO;

        // A fragments (hi/lo), 2 m16 tiles
        uint32_t ah[2][4], al[2][4];
        #pragma unroll
        for (int mt = 0; mt < 2; mt++) {
            const int r = wm + mt * 16 + (lane & 15);
            const int co = (lane >> 4) * 8;
            ldsm_x4(ah[mt], smem_u32(Ah + r * SSTR + co));
            ldsm_x4(al[mt], smem_u32(Al + r * SSTR + co));
        }
        // B fragments (hi/lo), 8 n8 tiles via 4 x4 loads per buffer
        uint32_t bh[8][2], bl[8][2];
        #pragma unroll
        for (int pr = 0; pr < 4; pr++) {
            const int r  = wn + pr * 16 + (lane & 7) + ((lane & 16) >> 1);
            const int co = lane & 8;
            uint32_t t[4];
            ldsm_x4(t, smem_u32(Bh + r * SSTR + co));
            bh[2*pr][0]=t[0]; bh[2*pr][1]=t[1]; bh[2*pr+1][0]=t[2]; bh[2*pr+1][1]=t[3];
            ldsm_x4(t, smem_u32(Bl + r * SSTR + co));
            bl[2*pr][0]=t[0]; bl[2*pr][1]=t[1]; bl[2*pr+1][0]=t[2]; bl[2*pr+1][1]=t[3];
        }

        // 3-pass bf16x3 MMAs
        #pragma unroll
        for (int mt = 0; mt < 2; mt++)
            #pragma unroll
            for (int nt = 0; nt < 8; nt++) {
                mma16816(acc[mt][nt], ah[mt], bh[nt]);
                mma16816(acc[mt][nt], ah[mt], bl[nt]);
                mma16816(acc[mt][nt], al[mt], bh[nt]);
            }

        // store prefetched tile into the other stage
        if (kt + 1 < KT) {
            const int nxt = (kt & 1) ? 0 : STAGE_ELEMS;
            cvt_store8(sm + nxt + arow * SSTR + akq,
                       sm + nxt + A_LO + arow * SSTR + akq, av);
            cvt_store8(sm + nxt + B_HI + bnn * SSTR + bkh,
                       sm + nxt + B_LO + bnn * SSTR + bkh, bv);
        }
        __syncthreads();
    }

    // ---- epilogue
    #pragma unroll
    for (int mt = 0; mt < 2; mt++) {
        const int r0 = bm + wm + mt * 16 + g;
        #pragma unroll
        for (int nt = 0; nt < 8; nt++) {
            const int c = bn + wn + nt * 8 + tg * 2;
            *(float2*)&C[(size_t)r0 * ldc + c] =
                make_float2(acc[mt][nt][0], acc[mt][nt][1]);
            *(float2*)&C[(size_t)(r0 + 8) * ldc + c] =
                make_float2(acc[mt][nt][2], acc[mt][nt][3]);
        }
    }
}

// ---------------- exact fp32 SGEMM (used ONLY for the 16 gate columns) ------
__global__ __launch_bounds__(256) void sgemm_kernel(
    const float* __restrict__ A, const float* __restrict__ B,
    float* __restrict__ C, int M, int N, int K, int ldb, int ldc)
{
    __shared__ float As[8][128];
    __shared__ float Bs[8][128];

    const int tid  = threadIdx.x;
    const int bm   = blockIdx.y * 128;
    const int bn   = blockIdx.x * 128;
    const int rowA = tid >> 1,  colA = (tid & 1) * 4;
    const int rowB = tid >> 5,  colB = (tid & 31) * 4;
    const int tr   = (tid >> 4) * 8;
    const int tc   = (tid & 15) * 8;

    float acc[8][8] = {};

    for (int k0 = 0; k0 < K; k0 += 8) {
        float4 a4 = *reinterpret_cast<const float4*>(
            A + (size_t)(bm + rowA) * K + k0 + colA);
        float4 b4 = make_float4(0.f, 0.f, 0.f, 0.f);
        if (bn + colB < N)
            b4 = *reinterpret_cast<const float4*>(
                B + (size_t)(k0 + rowB) * ldb + bn + colB);

        __syncthreads();
        As[colA + 0][rowA] = a4.x;
        As[colA + 1][rowA] = a4.y;
        As[colA + 2][rowA] = a4.z;
        As[colA + 3][rowA] = a4.w;
        *reinterpret_cast<float4*>(&Bs[rowB][colB]) = b4;
        __syncthreads();

        #pragma unroll
        for (int kk = 0; kk < 8; kk++) {
            float ar[8], br[8];
            *reinterpret_cast<float4*>(ar)     = *reinterpret_cast<const float4*>(&As[kk][tr]);
            *reinterpret_cast<float4*>(ar + 4) = *reinterpret_cast<const float4*>(&As[kk][tr + 4]);
            *reinterpret_cast<float4*>(br)     = *reinterpret_cast<const float4*>(&Bs[kk][tc]);
            *reinterpret_cast<float4*>(br + 4) = *reinterpret_cast<const float4*>(&Bs[kk][tc + 4]);
            #pragma unroll
            for (int i = 0; i < 8; i++)
                #pragma unroll
                for (int j = 0; j < 8; j++)
                    acc[i][j] = fmaf(ar[i], br[j], acc[i][j]);
        }
    }

    #pragma unroll
    for (int i = 0; i < 8; i++) {
        float* crow = C + (size_t)(bm + tr + i) * ldc + bn;
        #pragma unroll
        for (int j = 0; j < 8; j += 4) {
            if (bn + tc + j < N)
                *reinterpret_cast<float4*>(crow + tc + j) =
                    make_float4(acc[i][j], acc[i][j + 1], acc[i][j + 2], acc[i][j + 3]);
        }
    }
}

// ---------------- fused RMSNorm (full 2048-dim row) + NeoX RoPE ------------
__global__ __launch_bounds__(256) void norm_rope_kernel(
    float* __restrict__ qg, float* __restrict__ kb,
    const float* __restrict__ qw, const float* __restrict__ kw,
    const int* __restrict__ positions)
{
    const int t   = blockIdx.x;
    const int tid = threadIdx.x;
    __shared__ float red[256];
    __shared__ float cs[64], sn[64];
    __shared__ float rq_s, rk_s;

    float* qrow = qg + (size_t)t * NQG;
    float* krow = kb + (size_t)t * HID;

    float sq = 0.f, sk = 0.f;
    for (int i = tid; i < HID; i += 256) {
        float a = qrow[i]; sq = fmaf(a, a, sq);
        float b = krow[i]; sk = fmaf(b, b, sk);
    }
    red[tid] = sq; __syncthreads();
    for (int s = 128; s > 0; s >>= 1) { if (tid < s) red[tid] += red[tid + s]; __syncthreads(); }
    if (tid == 0) rq_s = rsqrtf(red[0] * (1.f / (float)HID) + 1e-6f);
    __syncthreads();
    red[tid] = sk; __syncthreads();
    for (int s = 128; s > 0; s >>= 1) { if (tid < s) red[tid] += red[tid + s]; __syncthreads(); }
    if (tid == 0) rk_s = rsqrtf(red[0] * (1.f / (float)HID) + 1e-6f);

    if (tid < 64) {
        double invf = exp(-(double)tid * (log(500000.0) / 64.0));
        double ang  = (double)positions[t] * invf;
        double sd, cd;
        sincos(ang, &sd, &cd);
        cs[tid] = (float)cd;
        sn[tid] = (float)sd;
    }
    __syncthreads();

    const float rq = rq_s, rk = rk_s;
    for (int pid = tid; pid < NH * 64; pid += 256) {
        int hh = pid >> 6, j = pid & 63;
        int i1 = hh * HD + j, i2 = i1 + 64;
        float c = cs[j], s = sn[j];
        float x1 = qrow[i1] * rq * qw[i1];
        float x2 = qrow[i2] * rq * qw[i2];
        qrow[i1] = x1 * c - x2 * s;
        qrow[i2] = x2 * c + x1 * s;
        float y1 = krow[i1] * rk * kw[i1];
        float y2 = krow[i2] * rk * kw[i2];
        krow[i1] = y1 * c - y2 * s;
        krow[i2] = y2 * c + y1 * s;
    }
}

// ---------------- dual (global causal + local window) flash attention -------
__global__ __launch_bounds__(128) void attn_kernel(
    const float* __restrict__ qg, const float* __restrict__ kb,
    const float* __restrict__ vb, float* __restrict__ outp,
    const int* __restrict__ positions)
{
    extern __shared__ float smem[];
    float* Qs = smem;                 // 32 x 128
    float* Ks = Qs + 32 * 128;        // 32 x 132 (padded)
    float* Vs = Ks + 32 * 132;        // 32 x 128
    int*  qpos = (int*)(Vs + 32 * 128);
    int*  kpos = qpos + 32;

    const int qb   = (int)gridDim.x - 1 - (int)blockIdx.x;
    const int h    = blockIdx.y;
    const int tid  = threadIdx.x;
    const int warp = tid >> 5, lane = tid & 31;
    const int r0   = warp * 8;
    const float scale = 0.08838834764831843f;

    for (int i = tid; i < 32 * 128; i += 128) {
        int r = i >> 7, c = i & 127;
        Qs[r * 128 + c] = qg[(size_t)(qb * 32 + r) * NQG + h * HD + c] * scale;
    }
    if (tid < 32) qpos[tid] = positions[qb * 32 + tid];

    float accg[8][4], accl[8][4], mg[8], lg[8], ml[8], ll[8];
    #pragma unroll
    for (int r = 0; r < 8; r++) {
        mg[r] = -1e30f; lg[r] = 0.f; ml[r] = -1e30f; ll[r] = 0.f;
        #pragma unroll
        for (int c = 0; c < 4; c++) { accg[r][c] = 0.f; accl[r][c] = 0.f; }
    }

    for (int kt = 0; kt <= qb; kt++) {
        __syncthreads();
        for (int i = tid; i < 32 * 128; i += 128) {
            int r = i >> 7, c = i & 127;
            size_t gi = (size_t)(kt * 32 + r) * HID + h * HD + c;
            Ks[r * 132 + c] = kb[gi];
            Vs[r * 128 + c] = vb[gi];
        }
        if (tid < 32) kpos[tid] = positions[kt * 32 + tid];
        __syncthreads();

        float s[8];
        #pragma unroll
        for (int r = 0; r < 8; r++) s[r] = 0.f;
        for (int c4 = 0; c4 < 128; c4 += 4) {
            float4 kv = *reinterpret_cast<const float4*>(&Ks[lane * 132 + c4]);
            #pragma unroll
            for (int r = 0; r < 8; r++) {
                float4 qv = *reinterpret_cast<const float4*>(&Qs[(r0 + r) * 128 + c4]);
                s[r] += qv.x * kv.x + qv.y * kv.y + qv.z * kv.z + qv.w * kv.w;
            }
        }

        const int  kp = kpos[lane];
        const bool local_tile = (kt >= qb - 4);
        float pg[8], pl[8];
        #pragma unroll
        for (int r = 0; r < 8; r++) {
            const int  qp     = qpos[r0 + r];
            const bool causal = (qp >= kp);
            const bool loc    = causal && (qp - kp < WIN);

            float sg = causal ? s[r] : -1e30f;
            float tmax = sg;
            #pragma unroll
            for (int o = 16; o > 0; o >>= 1)
                tmax = fmaxf(tmax, __shfl_xor_sync(0xffffffffu, tmax, o));
            float mnew  = fmaxf(mg[r], tmax);
            float alpha = __expf(mg[r] - mnew);
            float p     = causal ? __expf(s[r] - mnew) : 0.f;
            float psum  = p;
            #pragma unroll
            for (int o = 16; o > 0; o >>= 1)
                psum += __shfl_xor_sync(0xffffffffu, psum, o);
            lg[r] = lg[r] * alpha + psum;
            mg[r] = mnew;
            #pragma unroll
            for (int c = 0; c < 4; c++) accg[r][c] *= alpha;
            pg[r] = p;

            if (local_tile) {
                float sl = loc ? s[r] : -1e30f;
                float tml = sl;
                #pragma unroll
                for (int o = 16; o > 0; o >>= 1)
                    tml = fmaxf(tml, __shfl_xor_sync(0xffffffffu, tml, o));
                float mnl = fmaxf(ml[r], tml);
                float al  = __expf(ml[r] - mnl);
                float q   = loc ? __expf(s[r] - mnl) : 0.f;
                float qs  = q;
                #pragma unroll
                for (int o = 16; o > 0; o >>= 1)
                    qs += __shfl_xor_sync(0xffffffffu, qs, o);
                ll[r] = ll[r] * al + qs;
                ml[r] = mnl;
                #pragma unroll
                for (int c = 0; c < 4; c++) accl[r][c] *= al;
                pl[r] = q;
            }
        }

        #pragma unroll 4
        for (int key = 0; key < 32; key++) {
            float v0 = Vs[key * 128 + lane];
            float v1 = Vs[key * 128 + lane + 32];
            float v2 = Vs[key * 128 + lane + 64];
            float v3 = Vs[key * 128 + lane + 96];
            #pragma unroll
            for (int r = 0; r < 8; r++) {
                float w = __shfl_sync(0xffffffffu, pg[r], key);
                accg[r][0] = fmaf(w, v0, accg[r][0]);
                accg[r][1] = fmaf(w, v1, accg[r][1]);
                accg[r][2] = fmaf(w, v2, accg[r][2]);
                accg[r][3] = fmaf(w, v3, accg[r][3]);
            }
            if (local_tile) {
                #pragma unroll
                for (int r = 0; r < 8; r++) {
                    float w = __shfl_sync(0xffffffffu, pl[r], key);
                    accl[r][0] = fmaf(w, v0, accl[r][0]);
                    accl[r][1] = fmaf(w, v1, accl[r][1]);
                    accl[r][2] = fmaf(w, v2, accl[r][2]);
                    accl[r][3] = fmaf(w, v3, accl[r][3]);
                }
            }
        }
    }

    #pragma unroll
    for (int r = 0; r < 8; r++) {
        int t = qb * 32 + r0 + r;
        float g = qg[(size_t)t * NQG + NH * HD + h];
        bool useg = (g > 0.f);
        float inv = 1.f / (useg ? lg[r] : ll[r]);
        #pragma unroll
        for (int c = 0; c < 4; c++) {
            float val = (useg ? accg[r][c] : accl[r][c]) * inv;
            outp[(size_t)t * HID + h * HD + lane + c * 32] = val;
        }
    }
}

// ---------------------------------------------------------------------------
extern "C" void kernel_launch(void* const* d_in, const int* in_sizes, int n_in,
                              void* d_out, int out_size)
{
    const float* X   = (const float*)d_in[0];
    const int*   pos = (const int*)  d_in[1];
    const float* Wq  = (const float*)d_in[2];
    const float* Wk  = (const float*)d_in[3];
    const float* Wv  = (const float*)d_in[4];
    const float* Wo  = (const float*)d_in[5];
    const float* qw  = (const float*)d_in[6];
    const float* kw  = (const float*)d_in[7];
    float* out = (float*)d_out;

    float *qg, *kb, *vb, *bl;
    cudaGetSymbolAddress((void**)&qg, d_qg);
    cudaGetSymbolAddress((void**)&kb, d_kbuf);
    cudaGetSymbolAddress((void**)&vb, d_vbuf);
    cudaGetSymbolAddress((void**)&bl, d_blend);

    const int attn_smem = (32 * 128 + 32 * 132 + 32 * 128) * 4 + 64 * 4;
    cudaFuncSetAttribute(attn_kernel, cudaFuncAttributeMaxDynamicSharedMemorySize,
                         attn_smem);
    cudaFuncSetAttribute(mma_gemm, cudaFuncAttributeMaxDynamicSharedMemorySize,
                         GEMM_SMEM);

    dim3 blk(256);
    dim3 gtile(16, 16);   // 2048/128 x 2048/128

    // q columns (bf16x3 tensor cores) + exact fp32 gate columns
    mma_gemm<<<gtile, blk, GEMM_SMEM>>>(X, Wq, qg, HID, NQG, NQG);
    sgemm_kernel<<<dim3(1, 16), blk>>>(X, Wq + NH * HD, qg + NH * HD,
                                       T_TOK, NH, HID, NQG, NQG);
    mma_gemm<<<gtile, blk, GEMM_SMEM>>>(X, Wk, kb, HID, HID, HID);
    mma_gemm<<<gtile, blk, GEMM_SMEM>>>(X, Wv, vb, HID, HID, HID);

    norm_rope_kernel<<<T_TOK, 256>>>(qg, kb, qw, kw, pos);

    dim3 ga(T_TOK / 32, NH);
    attn_kernel<<<ga, 128, attn_smem>>>(qg, kb, vb, bl, pos);

    mma_gemm<<<gtile, blk, GEMM_SMEM>>>(bl, Wo, out, HID, HID, HID);
}

// round 5
// speedup vs baseline: 2.0004x; 1.6190x over previous
#include <cuda_runtime.h>
#include <cuda_bf16.h>
#include <math.h>
#include <stdint.h>

#define T_TOK 2048
#define HID   2048
#define NH    16
#define HD    128
#define NQG   2064      // H*D + H
#define WIN   128

// ---------------- scratch (static device globals; no runtime allocation) ----
__device__ float d_qg[T_TOK * NQG];     // X @ Wq  (gate cols 2048..2063 used later)
__device__ float d_kbuf[T_TOK * HID];   // X @ Wk (pre-norm)
__device__ float d_vbuf[T_TOK * HID];   // X @ Wv
__device__ float d_blend[T_TOK * HID];  // gated attention output

// bf16 hi/lo split buffers (Q has softmax scale folded in)
__device__ __nv_bfloat16 d_Qh[T_TOK * HID];
__device__ __nv_bfloat16 d_Ql[T_TOK * HID];
__device__ __nv_bfloat16 d_Kh[T_TOK * HID];
__device__ __nv_bfloat16 d_Kl[T_TOK * HID];
__device__ __nv_bfloat16 d_Vh[T_TOK * HID];
__device__ __nv_bfloat16 d_Vl[T_TOK * HID];

// ---------------- common MMA helpers ---------------------------------------
__device__ __forceinline__ uint32_t smem_u32(const void* p) {
    return (uint32_t)__cvta_generic_to_shared(p);
}
__device__ __forceinline__ void ldsm_x4(uint32_t* r, uint32_t addr) {
    asm volatile("ldmatrix.sync.aligned.m8n8.x4.shared.b16 {%0,%1,%2,%3}, [%4];\n"
        : "=r"(r[0]), "=r"(r[1]), "=r"(r[2]), "=r"(r[3]) : "r"(addr));
}
__device__ __forceinline__ void ldsm_x4_t(uint32_t* r, uint32_t addr) {
    asm volatile("ldmatrix.sync.aligned.m8n8.x4.trans.shared.b16 {%0,%1,%2,%3}, [%4];\n"
        : "=r"(r[0]), "=r"(r[1]), "=r"(r[2]), "=r"(r[3]) : "r"(addr));
}
__device__ __forceinline__ void mma16816(float* d, const uint32_t* a, const uint32_t* b) {
    asm volatile(
        "mma.sync.aligned.m16n8k16.row.col.f32.bf16.bf16.f32 "
        "{%0,%1,%2,%3}, {%4,%5,%6,%7}, {%8,%9}, {%0,%1,%2,%3};\n"
        : "+f"(d[0]), "+f"(d[1]), "+f"(d[2]), "+f"(d[3])
        : "r"(a[0]), "r"(a[1]), "r"(a[2]), "r"(a[3]), "r"(b[0]), "r"(b[1]));
}
__device__ __forceinline__ void split2(float a, float b, uint32_t& hi, uint32_t& lo) {
    __nv_bfloat16 ha = __float2bfloat16(a), hb = __float2bfloat16(b);
    __nv_bfloat162 H, L;
    H.x = ha; H.y = hb;
    L.x = __float2bfloat16(a - __bfloat162float(ha));
    L.y = __float2bfloat16(b - __bfloat162float(hb));
    hi = *(uint32_t*)&H; lo = *(uint32_t*)&L;
}
__device__ __forceinline__ void cvt_store8(__nv_bfloat16* hi, __nv_bfloat16* lo,
                                           const float* v) {
    union { __nv_bfloat16 b[8]; uint4 u; } ph, pl;
    #pragma unroll
    for (int j = 0; j < 8; j++) {
        __nv_bfloat16 h = __float2bfloat16(v[j]);
        ph.b[j] = h;
        pl.b[j] = __float2bfloat16(v[j] - __bfloat162float(h));
    }
    *(uint4*)hi = ph.u;
    *(uint4*)lo = pl.u;
}

// ============================================================================
// bf16x3 tensor-core GEMM (fp32 in/out), 128x128 tile, BK=16, 256 threads.
// ============================================================================
#define SSTR 24
#define STAGE_ELEMS (4 * 128 * SSTR)
#define GEMM_SMEM (2 * STAGE_ELEMS * 2)

__global__ __launch_bounds__(256, 2) void mma_gemm(
    const float* __restrict__ A, const float* __restrict__ B,
    float* __restrict__ C, int K, int ldb, int ldc)
{
    extern __shared__ char smraw[];
    __nv_bfloat16* sm = (__nv_bfloat16*)smraw;

    const int tid  = threadIdx.x;
    const int warp = tid >> 5, lane = tid & 31;
    const int bm   = blockIdx.y * 128, bn = blockIdx.x * 128;

    const int A_LO = 128 * SSTR;
    const int B_HI = 2 * 128 * SSTR;
    const int B_LO = 3 * 128 * SSTR;

    const int arow = tid >> 1;
    const int akq  = (tid & 1) * 8;
    const int bnn  = tid & 127;
    const int bkh  = (tid >> 7) * 8;

    const int wm = (warp & 3) * 32;
    const int wn = (warp >> 2) * 64;
    const int g  = lane >> 2, tg = lane & 3;

    float acc[2][8][4];
    #pragma unroll
    for (int mt = 0; mt < 2; mt++)
        #pragma unroll
        for (int nt = 0; nt < 8; nt++)
            #pragma unroll
            for (int i = 0; i < 4; i++) acc[mt][nt][i] = 0.f;

    float av[8], bv[8];
    {
        const float* ap = A + (size_t)(bm + arow) * K + akq;
        float4 x = *(const float4*)ap;
        float4 y = *(const float4*)(ap + 4);
        av[0]=x.x; av[1]=x.y; av[2]=x.z; av[3]=x.w;
        av[4]=y.x; av[5]=y.y; av[6]=y.z; av[7]=y.w;
        const float* bp = B + (size_t)bkh * ldb + bn + bnn;
        #pragma unroll
        for (int j = 0; j < 8; j++) bv[j] = bp[(size_t)j * ldb];
    }
    cvt_store8(sm + arow * SSTR + akq, sm + A_LO + arow * SSTR + akq, av);
    cvt_store8(sm + B_HI + bnn * SSTR + bkh, sm + B_LO + bnn * SSTR + bkh, bv);
    __syncthreads();

    const int KT = K >> 4;
    for (int kt = 0; kt < KT; kt++) {
        const int cur = (kt & 1) ? STAGE_ELEMS : 0;

        if (kt + 1 < KT) {
            const int k0 = (kt + 1) << 4;
            const float* ap = A + (size_t)(bm + arow) * K + k0 + akq;
            float4 x = *(const float4*)ap;
            float4 y = *(const float4*)(ap + 4);
            av[0]=x.x; av[1]=x.y; av[2]=x.z; av[3]=x.w;
            av[4]=y.x; av[5]=y.y; av[6]=y.z; av[7]=y.w;
            const float* bp = B + (size_t)(k0 + bkh) * ldb + bn + bnn;
            #pragma unroll
            for (int j = 0; j < 8; j++) bv[j] = bp[(size_t)j * ldb];
        }

        const __nv_bfloat16* Ah = sm + cur;
        const __nv_bfloat16* Al = Ah + A_LO;
        const __nv_bfloat16* Bh = sm + cur + B_HI;
        const __nv_bfloat16* Bl = sm + cur + B_LO;

        uint32_t ah[2][4], al[2][4];
        #pragma unroll
        for (int mt = 0; mt < 2; mt++) {
            const int r = wm + mt * 16 + (lane & 15);
            const int co = (lane >> 4) * 8;
            ldsm_x4(ah[mt], smem_u32(Ah + r * SSTR + co));
            ldsm_x4(al[mt], smem_u32(Al + r * SSTR + co));
        }
        uint32_t bh[8][2], bl[8][2];
        #pragma unroll
        for (int pr = 0; pr < 4; pr++) {
            const int r  = wn + pr * 16 + (lane & 7) + ((lane & 16) >> 1);
            const int co = lane & 8;
            uint32_t t[4];
            ldsm_x4(t, smem_u32(Bh + r * SSTR + co));
            bh[2*pr][0]=t[0]; bh[2*pr][1]=t[1]; bh[2*pr+1][0]=t[2]; bh[2*pr+1][1]=t[3];
            ldsm_x4(t, smem_u32(Bl + r * SSTR + co));
            bl[2*pr][0]=t[0]; bl[2*pr][1]=t[1]; bl[2*pr+1][0]=t[2]; bl[2*pr+1][1]=t[3];
        }

        #pragma unroll
        for (int mt = 0; mt < 2; mt++)
            #pragma unroll
            for (int nt = 0; nt < 8; nt++) {
                mma16816(acc[mt][nt], ah[mt], bh[nt]);
                mma16816(acc[mt][nt], ah[mt], bl[nt]);
                mma16816(acc[mt][nt], al[mt], bh[nt]);
            }

        if (kt + 1 < KT) {
            const int nxt = (kt & 1) ? 0 : STAGE_ELEMS;
            cvt_store8(sm + nxt + arow * SSTR + akq,
                       sm + nxt + A_LO + arow * SSTR + akq, av);
            cvt_store8(sm + nxt + B_HI + bnn * SSTR + bkh,
                       sm + nxt + B_LO + bnn * SSTR + bkh, bv);
        }
        __syncthreads();
    }

    #pragma unroll
    for (int mt = 0; mt < 2; mt++) {
        const int r0 = bm + wm + mt * 16 + g;
        #pragma unroll
        for (int nt = 0; nt < 8; nt++) {
            const int c = bn + wn + nt * 8 + tg * 2;
            *(float2*)&C[(size_t)r0 * ldc + c] =
                make_float2(acc[mt][nt][0], acc[mt][nt][1]);
            *(float2*)&C[(size_t)(r0 + 8) * ldc + c] =
                make_float2(acc[mt][nt][2], acc[mt][nt][3]);
        }
    }
}

// ---------------- exact fp32 SGEMM (gate columns only) ----------------------
__global__ __launch_bounds__(256) void sgemm_kernel(
    const float* __restrict__ A, const float* __restrict__ B,
    float* __restrict__ C, int M, int N, int K, int ldb, int ldc)
{
    __shared__ float As[8][128];
    __shared__ float Bs[8][128];

    const int tid  = threadIdx.x;
    const int bm   = blockIdx.y * 128;
    const int bn   = blockIdx.x * 128;
    const int rowA = tid >> 1,  colA = (tid & 1) * 4;
    const int rowB = tid >> 5,  colB = (tid & 31) * 4;
    const int tr   = (tid >> 4) * 8;
    const int tc   = (tid & 15) * 8;

    float acc[8][8] = {};

    for (int k0 = 0; k0 < K; k0 += 8) {
        float4 a4 = *reinterpret_cast<const float4*>(
            A + (size_t)(bm + rowA) * K + k0 + colA);
        float4 b4 = make_float4(0.f, 0.f, 0.f, 0.f);
        if (bn + colB < N)
            b4 = *reinterpret_cast<const float4*>(
                B + (size_t)(k0 + rowB) * ldb + bn + colB);

        __syncthreads();
        As[colA + 0][rowA] = a4.x;
        As[colA + 1][rowA] = a4.y;
        As[colA + 2][rowA] = a4.z;
        As[colA + 3][rowA] = a4.w;
        *reinterpret_cast<float4*>(&Bs[rowB][colB]) = b4;
        __syncthreads();

        #pragma unroll
        for (int kk = 0; kk < 8; kk++) {
            float ar[8], br[8];
            *reinterpret_cast<float4*>(ar)     = *reinterpret_cast<const float4*>(&As[kk][tr]);
            *reinterpret_cast<float4*>(ar + 4) = *reinterpret_cast<const float4*>(&As[kk][tr + 4]);
            *reinterpret_cast<float4*>(br)     = *reinterpret_cast<const float4*>(&Bs[kk][tc]);
            *reinterpret_cast<float4*>(br + 4) = *reinterpret_cast<const float4*>(&Bs[kk][tc + 4]);
            #pragma unroll
            for (int i = 0; i < 8; i++)
                #pragma unroll
                for (int j = 0; j < 8; j++)
                    acc[i][j] = fmaf(ar[i], br[j], acc[i][j]);
        }
    }

    #pragma unroll
    for (int i = 0; i < 8; i++) {
        float* crow = C + (size_t)(bm + tr + i) * ldc + bn;
        #pragma unroll
        for (int j = 0; j < 8; j += 4) {
            if (bn + tc + j < N)
                *reinterpret_cast<float4*>(crow + tc + j) =
                    make_float4(acc[i][j], acc[i][j + 1], acc[i][j + 2], acc[i][j + 3]);
        }
    }
}

// ---------------- RMSNorm + RoPE + bf16 hi/lo split (q,k,v) ----------------
__global__ __launch_bounds__(256) void norm_rope_kernel(
    const float* __restrict__ qg, const float* __restrict__ kb,
    const float* __restrict__ vb,
    const float* __restrict__ qw, const float* __restrict__ kw,
    const int* __restrict__ positions,
    __nv_bfloat16* __restrict__ Qh, __nv_bfloat16* __restrict__ Ql,
    __nv_bfloat16* __restrict__ Kh, __nv_bfloat16* __restrict__ Kl,
    __nv_bfloat16* __restrict__ Vh, __nv_bfloat16* __restrict__ Vl)
{
    const int t   = blockIdx.x;
    const int tid = threadIdx.x;
    __shared__ float red[256];
    __shared__ float cs[64], sn[64];
    __shared__ float rq_s, rk_s;

    const float* qrow = qg + (size_t)t * NQG;
    const float* krow = kb + (size_t)t * HID;
    const float* vrow = vb + (size_t)t * HID;
    const float scale = 0.08838834764831843f;

    float sq = 0.f, sk = 0.f;
    for (int i = tid; i < HID; i += 256) {
        float a = qrow[i]; sq = fmaf(a, a, sq);
        float b = krow[i]; sk = fmaf(b, b, sk);
    }
    red[tid] = sq; __syncthreads();
    for (int s = 128; s > 0; s >>= 1) { if (tid < s) red[tid] += red[tid + s]; __syncthreads(); }
    if (tid == 0) rq_s = rsqrtf(red[0] * (1.f / (float)HID) + 1e-6f);
    __syncthreads();
    red[tid] = sk; __syncthreads();
    for (int s = 128; s > 0; s >>= 1) { if (tid < s) red[tid] += red[tid + s]; __syncthreads(); }
    if (tid == 0) rk_s = rsqrtf(red[0] * (1.f / (float)HID) + 1e-6f);

    if (tid < 64) {
        double invf = exp(-(double)tid * (log(500000.0) / 64.0));
        double ang  = (double)positions[t] * invf;
        double sd, cd;
        sincos(ang, &sd, &cd);
        cs[tid] = (float)cd;
        sn[tid] = (float)sd;
    }
    __syncthreads();

    const float rq = rq_s, rk = rk_s;
    for (int pid = tid; pid < NH * 64; pid += 256) {
        int hh = pid >> 6, j = pid & 63;
        int i1 = hh * HD + j, i2 = i1 + 64;
        float c = cs[j], s = sn[j];
        float x1 = qrow[i1] * rq * qw[i1];
        float x2 = qrow[i2] * rq * qw[i2];
        float q1 = (x1 * c - x2 * s) * scale;
        float q2 = (x2 * c + x1 * s) * scale;
        float y1 = krow[i1] * rk * kw[i1];
        float y2 = krow[i2] * rk * kw[i2];
        float k1 = y1 * c - y2 * s;
        float k2 = y2 * c + y1 * s;

        size_t b = (size_t)t * HID;
        __nv_bfloat16 h;
        h = __float2bfloat16(q1); Qh[b+i1] = h; Ql[b+i1] = __float2bfloat16(q1 - __bfloat162float(h));
        h = __float2bfloat16(q2); Qh[b+i2] = h; Ql[b+i2] = __float2bfloat16(q2 - __bfloat162float(h));
        h = __float2bfloat16(k1); Kh[b+i1] = h; Kl[b+i1] = __float2bfloat16(k1 - __bfloat162float(h));
        h = __float2bfloat16(k2); Kh[b+i2] = h; Kl[b+i2] = __float2bfloat16(k2 - __bfloat162float(h));
    }
    for (int i = tid; i < HID; i += 256) {
        float v = vrow[i];
        __nv_bfloat16 h = __float2bfloat16(v);
        size_t b = (size_t)t * HID + i;
        Vh[b] = h; Vl[b] = __float2bfloat16(v - __bfloat162float(h));
    }
}

// ============================================================================
// Tensor-core dual attention.  One CTA = (head h, 64-query block).
// 4 warps x 16 rows.  Pass 0 = local (<=3 key tiles, writes rows gate<=0);
// pass 1 = global causal (writes rows gate>0).  bf16x3 for QK^T and PV.
// ============================================================================
#define BR 64
#define BC 64
#define ASTR 136
#define ATTN_SMEM (6 * BR * ASTR * 2 + (BR + BC) * 4 + BR * 4)

__global__ __launch_bounds__(128, 2) void attn_mma_kernel(
    const __nv_bfloat16* __restrict__ Qh, const __nv_bfloat16* __restrict__ Ql,
    const __nv_bfloat16* __restrict__ Kh, const __nv_bfloat16* __restrict__ Kl,
    const __nv_bfloat16* __restrict__ Vh, const __nv_bfloat16* __restrict__ Vl,
    const float* __restrict__ qg, float* __restrict__ outp,
    const int* __restrict__ positions)
{
    extern __shared__ char smraw[];
    __nv_bfloat16* sQh = (__nv_bfloat16*)smraw;
    __nv_bfloat16* sQl = sQh + BR * ASTR;
    __nv_bfloat16* sKh = sQl + BR * ASTR;
    __nv_bfloat16* sKl = sKh + BC * ASTR;
    __nv_bfloat16* sVh = sKl + BC * ASTR;
    __nv_bfloat16* sVl = sVh + BC * ASTR;
    int*   qpos_s = (int*)(sVl + BC * ASTR);
    int*   kpos_s = qpos_s + BR;
    float* gate_s = (float*)(kpos_s + BC);

    const int qb   = (int)gridDim.x - 1 - (int)blockIdx.x;  // heavy blocks first
    const int h    = blockIdx.y;
    const int tid  = threadIdx.x;
    const int warp = tid >> 5, lane = tid & 31;
    const int g = lane >> 2, tg = lane & 3;

    // ---- load Q tile (hi/lo), positions, gates
    {
        const int row = tid >> 1, half = (tid & 1) * 64;
        const size_t gb = (size_t)(qb * BR + row) * HID + h * HD + half;
        #pragma unroll
        for (int i = 0; i < 8; i++) {
            *(uint4*)&sQh[row * ASTR + half + i * 8] = *(const uint4*)(Qh + gb + i * 8);
            *(uint4*)&sQl[row * ASTR + half + i * 8] = *(const uint4*)(Ql + gb + i * 8);
        }
        if (tid < BR) {
            qpos_s[tid] = positions[qb * BR + tid];
            gate_s[tid] = qg[(size_t)(qb * BR + tid) * NQG + NH * HD + h];
        }
    }

    const uint32_t aQh = smem_u32(sQh + (warp * 16 + (lane & 15)) * ASTR + (lane >> 4) * 8);
    const uint32_t aQl = smem_u32(sQl + (warp * 16 + (lane & 15)) * ASTR + (lane >> 4) * 8);
    const int bKrow = (lane & 7) + ((lane & 16) >> 1);
    const int bKco  = lane & 8;
    const int vKrow = (lane & 8) + (lane & 7);       // key row within 16-chunk
    const int vDco  = (lane & 16) >> 1;              // +8 d for lanes 16..31

    for (int pass = 0; pass < 2; pass++) {
        const int kt0 = (pass == 0) ? max(0, qb - 2) : 0;
        const int win = (pass == 0) ? WIN : (1 << 30);

        float m0 = -1e30f, m1 = -1e30f, l0 = 0.f, l1 = 0.f;
        float o[16][4];
        #pragma unroll
        for (int nt = 0; nt < 16; nt++)
            #pragma unroll
            for (int i = 0; i < 4; i++) o[nt][i] = 0.f;

        for (int kt = kt0; kt <= qb; kt++) {
            __syncthreads();
            {
                const int row = tid >> 1, half = (tid & 1) * 64;
                const size_t gb = (size_t)(kt * BC + row) * HID + h * HD + half;
                #pragma unroll
                for (int i = 0; i < 8; i++) {
                    *(uint4*)&sKh[row * ASTR + half + i * 8] = *(const uint4*)(Kh + gb + i * 8);
                    *(uint4*)&sKl[row * ASTR + half + i * 8] = *(const uint4*)(Kl + gb + i * 8);
                    *(uint4*)&sVh[row * ASTR + half + i * 8] = *(const uint4*)(Vh + gb + i * 8);
                    *(uint4*)&sVl[row * ASTR + half + i * 8] = *(const uint4*)(Vl + gb + i * 8);
                }
                if (tid < BC) kpos_s[tid] = positions[kt * BC + tid];
            }
            __syncthreads();

            // ---- S = Q K^T (bf16x3)
            float s[8][4];
            #pragma unroll
            for (int nt = 0; nt < 8; nt++)
                #pragma unroll
                for (int i = 0; i < 4; i++) s[nt][i] = 0.f;

            #pragma unroll
            for (int kk = 0; kk < 8; kk++) {
                uint32_t ah[4], al[4];
                ldsm_x4(ah, aQh + kk * 32);           // 16 bf16 = 32 bytes
                ldsm_x4(al, aQl + kk * 32);
                uint32_t bh[8][2], bl[8][2];
                #pragma unroll
                for (int pr = 0; pr < 4; pr++) {
                    const int r = pr * 16 + bKrow;
                    uint32_t t4[4];
                    ldsm_x4(t4, smem_u32(sKh + r * ASTR + kk * 16 + bKco));
                    bh[2*pr][0]=t4[0]; bh[2*pr][1]=t4[1]; bh[2*pr+1][0]=t4[2]; bh[2*pr+1][1]=t4[3];
                    ldsm_x4(t4, smem_u32(sKl + r * ASTR + kk * 16 + bKco));
                    bl[2*pr][0]=t4[0]; bl[2*pr][1]=t4[1]; bl[2*pr+1][0]=t4[2]; bl[2*pr+1][1]=t4[3];
                }
                #pragma unroll
                for (int nt = 0; nt < 8; nt++) {
                    mma16816(s[nt], ah, bh[nt]);
                    mma16816(s[nt], ah, bl[nt]);
                    mma16816(s[nt], al, bh[nt]);
                }
            }

            // ---- masking
            const bool needmask = (pass == 0) || (kt == qb);
            if (needmask) {
                const int qp0 = qpos_s[warp * 16 + g];
                const int qp1 = qpos_s[warp * 16 + g + 8];
                #pragma unroll
                for (int nt = 0; nt < 8; nt++) {
                    #pragma unroll
                    for (int j = 0; j < 2; j++) {
                        const int kp = kpos_s[8 * nt + 2 * tg + j];
                        if (!(qp0 >= kp && qp0 - kp < win)) s[nt][j]     = -1e30f;
                        if (!(qp1 >= kp && qp1 - kp < win)) s[nt][2 + j] = -1e30f;
                    }
                }
            }

            // ---- online softmax (rows g, g+8), reductions within quad
            float mx0 = -1e30f, mx1 = -1e30f;
            #pragma unroll
            for (int nt = 0; nt < 8; nt++) {
                mx0 = fmaxf(mx0, fmaxf(s[nt][0], s[nt][1]));
                mx1 = fmaxf(mx1, fmaxf(s[nt][2], s[nt][3]));
            }
            mx0 = fmaxf(mx0, __shfl_xor_sync(0xffffffffu, mx0, 1));
            mx0 = fmaxf(mx0, __shfl_xor_sync(0xffffffffu, mx0, 2));
            mx1 = fmaxf(mx1, __shfl_xor_sync(0xffffffffu, mx1, 1));
            mx1 = fmaxf(mx1, __shfl_xor_sync(0xffffffffu, mx1, 2));

            const float mn0 = fmaxf(fmaxf(m0, mx0), -1e28f);
            const float mn1 = fmaxf(fmaxf(m1, mx1), -1e28f);
            const float al0 = __expf(m0 - mn0);
            const float al1 = __expf(m1 - mn1);
            float sum0 = 0.f, sum1 = 0.f;
            #pragma unroll
            for (int nt = 0; nt < 8; nt++) {
                s[nt][0] = __expf(s[nt][0] - mn0); sum0 += s[nt][0];
                s[nt][1] = __expf(s[nt][1] - mn0); sum0 += s[nt][1];
                s[nt][2] = __expf(s[nt][2] - mn1); sum1 += s[nt][2];
                s[nt][3] = __expf(s[nt][3] - mn1); sum1 += s[nt][3];
            }
            sum0 += __shfl_xor_sync(0xffffffffu, sum0, 1);
            sum0 += __shfl_xor_sync(0xffffffffu, sum0, 2);
            sum1 += __shfl_xor_sync(0xffffffffu, sum1, 1);
            sum1 += __shfl_xor_sync(0xffffffffu, sum1, 2);
            l0 = l0 * al0 + sum0; m0 = mn0;
            l1 = l1 * al1 + sum1; m1 = mn1;
            #pragma unroll
            for (int nt = 0; nt < 16; nt++) {
                o[nt][0] *= al0; o[nt][1] *= al0;
                o[nt][2] *= al1; o[nt][3] *= al1;
            }

            // ---- O += P V (bf16x3), P from S accumulators (no shuffles)
            #pragma unroll
            for (int kk = 0; kk < 4; kk++) {
                uint32_t ahi[4], alo[4];
                split2(s[2*kk][0],   s[2*kk][1],   ahi[0], alo[0]);
                split2(s[2*kk][2],   s[2*kk][3],   ahi[1], alo[1]);
                split2(s[2*kk+1][0], s[2*kk+1][1], ahi[2], alo[2]);
                split2(s[2*kk+1][2], s[2*kk+1][3], ahi[3], alo[3]);
                #pragma unroll
                for (int dn = 0; dn < 8; dn++) {
                    uint32_t v4[4];
                    ldsm_x4_t(v4, smem_u32(sVh + (kk * 16 + vKrow) * ASTR + dn * 16 + vDco));
                    mma16816(o[2*dn],     ahi, &v4[0]);
                    mma16816(o[2*dn + 1], ahi, &v4[2]);
                    mma16816(o[2*dn],     alo, &v4[0]);
                    mma16816(o[2*dn + 1], alo, &v4[2]);
                    ldsm_x4_t(v4, smem_u32(sVl + (kk * 16 + vKrow) * ASTR + dn * 16 + vDco));
                    mma16816(o[2*dn],     ahi, &v4[0]);
                    mma16816(o[2*dn + 1], ahi, &v4[2]);
                }
            }
        }

        // ---- epilogue: this pass writes only its gate-selected rows
        const bool isglobal = (pass == 1);
        const float inv0 = 1.f / l0, inv1 = 1.f / l1;
        const bool wr0 = (gate_s[warp * 16 + g]     > 0.f) == isglobal;
        const bool wr1 = (gate_s[warp * 16 + g + 8] > 0.f) == isglobal;
        const int t0 = qb * BR + warp * 16 + g;
        #pragma unroll
        for (int nt = 0; nt < 16; nt++) {
            const int d = 8 * nt + 2 * tg;
            if (wr0)
                *(float2*)&outp[(size_t)t0 * HID + h * HD + d] =
                    make_float2(o[nt][0] * inv0, o[nt][1] * inv0);
            if (wr1)
                *(float2*)&outp[(size_t)(t0 + 8) * HID + h * HD + d] =
                    make_float2(o[nt][2] * inv1, o[nt][3] * inv1);
        }
    }
}

// ---------------------------------------------------------------------------
extern "C" void kernel_launch(void* const* d_in, const int* in_sizes, int n_in,
                              void* d_out, int out_size)
{
    const float* X   = (const float*)d_in[0];
    const int*   pos = (const int*)  d_in[1];
    const float* Wq  = (const float*)d_in[2];
    const float* Wk  = (const float*)d_in[3];
    const float* Wv  = (const float*)d_in[4];
    const float* Wo  = (const float*)d_in[5];
    const float* qw  = (const float*)d_in[6];
    const float* kw  = (const float*)d_in[7];
    float* out = (float*)d_out;

    float *qg, *kb, *vb, *bl;
    __nv_bfloat16 *Qh, *Ql, *Kh, *Kl, *Vh, *Vl;
    cudaGetSymbolAddress((void**)&qg, d_qg);
    cudaGetSymbolAddress((void**)&kb, d_kbuf);
    cudaGetSymbolAddress((void**)&vb, d_vbuf);
    cudaGetSymbolAddress((void**)&bl, d_blend);
    cudaGetSymbolAddress((void**)&Qh, d_Qh);
    cudaGetSymbolAddress((void**)&Ql, d_Ql);
    cudaGetSymbolAddress((void**)&Kh, d_Kh);
    cudaGetSymbolAddress((void**)&Kl, d_Kl);
    cudaGetSymbolAddress((void**)&Vh, d_Vh);
    cudaGetSymbolAddress((void**)&Vl, d_Vl);

    cudaFuncSetAttribute(mma_gemm, cudaFuncAttributeMaxDynamicSharedMemorySize,
                         GEMM_SMEM);
    cudaFuncSetAttribute(attn_mma_kernel, cudaFuncAttributeMaxDynamicSharedMemorySize,
                         ATTN_SMEM);

    dim3 blk(256);
    dim3 gtile(16, 16);

    mma_gemm<<<gtile, blk, GEMM_SMEM>>>(X, Wq, qg, HID, NQG, NQG);
    sgemm_kernel<<<dim3(1, 16), blk>>>(X, Wq + NH * HD, qg + NH * HD,
                                       T_TOK, NH, HID, NQG, NQG);
    mma_gemm<<<gtile, blk, GEMM_SMEM>>>(X, Wk, kb, HID, HID, HID);
    mma_gemm<<<gtile, blk, GEMM_SMEM>>>(X, Wv, vb, HID, HID, HID);

    norm_rope_kernel<<<T_TOK, 256>>>(qg, kb, vb, qw, kw, pos,
                                     Qh, Ql, Kh, Kl, Vh, Vl);

    dim3 ga(T_TOK / BR, NH);   // 32 x 16
    attn_mma_kernel<<<ga, 128, ATTN_SMEM>>>(Qh, Ql, Kh, Kl, Vh, Vl,
                                            qg, bl, pos);

    mma_gemm<<<gtile, blk, GEMM_SMEM>>>(bl, Wo, out, HID, HID, HID);
}

// round 6
// speedup vs baseline: 2.0282x; 1.0139x over previous
#include <cuda_runtime.h>
#include <cuda_bf16.h>
#include <math.h>
#include <stdint.h>

#define T_TOK 2048
#define HID   2048
#define NH    16
#define HD    128
#define NQG   2064      // H*D + H
#define WIN   128

// ---------------- scratch (static device globals; no runtime allocation) ----
__device__ float d_qg[T_TOK * NQG];     // X @ Wq  (gate cols 2048..2063)
__device__ float d_kbuf[T_TOK * HID];   // X @ Wk (pre-norm)
__device__ float d_vbuf[T_TOK * HID];   // X @ Wv
__device__ float d_blend[T_TOK * HID];  // gated attention output

__device__ __nv_bfloat16 d_Qh[T_TOK * HID];
__device__ __nv_bfloat16 d_Ql[T_TOK * HID];
__device__ __nv_bfloat16 d_Kh[T_TOK * HID];
__device__ __nv_bfloat16 d_Kl[T_TOK * HID];
__device__ __nv_bfloat16 d_Vh[T_TOK * HID];
__device__ __nv_bfloat16 d_Vl[T_TOK * HID];

// ---------------- common helpers -------------------------------------------
__device__ __forceinline__ uint32_t smem_u32(const void* p) {
    return (uint32_t)__cvta_generic_to_shared(p);
}
__device__ __forceinline__ void ldsm_x4(uint32_t* r, uint32_t addr) {
    asm volatile("ldmatrix.sync.aligned.m8n8.x4.shared.b16 {%0,%1,%2,%3}, [%4];\n"
        : "=r"(r[0]), "=r"(r[1]), "=r"(r[2]), "=r"(r[3]) : "r"(addr));
}
__device__ __forceinline__ void ldsm_x4_t(uint32_t* r, uint32_t addr) {
    asm volatile("ldmatrix.sync.aligned.m8n8.x4.trans.shared.b16 {%0,%1,%2,%3}, [%4];\n"
        : "=r"(r[0]), "=r"(r[1]), "=r"(r[2]), "=r"(r[3]) : "r"(addr));
}
__device__ __forceinline__ void mma16816(float* d, const uint32_t* a, const uint32_t* b) {
    asm volatile(
        "mma.sync.aligned.m16n8k16.row.col.f32.bf16.bf16.f32 "
        "{%0,%1,%2,%3}, {%4,%5,%6,%7}, {%8,%9}, {%0,%1,%2,%3};\n"
        : "+f"(d[0]), "+f"(d[1]), "+f"(d[2]), "+f"(d[3])
        : "r"(a[0]), "r"(a[1]), "r"(a[2]), "r"(a[3]), "r"(b[0]), "r"(b[1]));
}
__device__ __forceinline__ void split2(float a, float b, uint32_t& hi, uint32_t& lo) {
    __nv_bfloat16 ha = __float2bfloat16(a), hb = __float2bfloat16(b);
    __nv_bfloat162 H, L;
    H.x = ha; H.y = hb;
    L.x = __float2bfloat16(a - __bfloat162float(ha));
    L.y = __float2bfloat16(b - __bfloat162float(hb));
    hi = *(uint32_t*)&H; lo = *(uint32_t*)&L;
}
__device__ __forceinline__ void cvt_store8(__nv_bfloat16* hi, __nv_bfloat16* lo,
                                           const float* v) {
    union { __nv_bfloat16 b[8]; uint4 u; } ph, pl;
    #pragma unroll
    for (int j = 0; j < 8; j++) {
        __nv_bfloat16 h = __float2bfloat16(v[j]);
        ph.b[j] = h;
        pl.b[j] = __float2bfloat16(v[j] - __bfloat162float(h));
    }
    *(uint4*)hi = ph.u;
    *(uint4*)lo = pl.u;
}
__device__ __forceinline__ void cpa16(uint32_t dst, const void* src) {
    asm volatile("cp.async.cg.shared.global [%0], [%1], 16;\n" :: "r"(dst), "l"(src));
}
__device__ __forceinline__ void cp_commit() {
    asm volatile("cp.async.commit_group;\n" ::: "memory");
}
__device__ __forceinline__ void cp_wait1() {
    asm volatile("cp.async.wait_group 1;\n" ::: "memory");
}

// ============================================================================
// bf16x3 tensor-core GEMM (fp32 in/out), 128x128 tile, BK=16, 256 threads.
// ============================================================================
#define SSTR 24
#define STAGE_ELEMS (4 * 128 * SSTR)
#define GEMM_SMEM (2 * STAGE_ELEMS * 2)

__global__ __launch_bounds__(256, 2) void mma_gemm(
    const float* __restrict__ A, const float* __restrict__ B,
    float* __restrict__ C, int K, int ldb, int ldc)
{
    extern __shared__ char smraw[];
    __nv_bfloat16* sm = (__nv_bfloat16*)smraw;

    const int tid  = threadIdx.x;
    const int warp = tid >> 5, lane = tid & 31;
    const int bm   = blockIdx.y * 128, bn = blockIdx.x * 128;

    const int A_LO = 128 * SSTR;
    const int B_HI = 2 * 128 * SSTR;
    const int B_LO = 3 * 128 * SSTR;

    const int arow = tid >> 1;
    const int akq  = (tid & 1) * 8;
    const int bnn  = tid & 127;
    const int bkh  = (tid >> 7) * 8;

    const int wm = (warp & 3) * 32;
    const int wn = (warp >> 2) * 64;
    const int g  = lane >> 2, tg = lane & 3;

    float acc[2][8][4];
    #pragma unroll
    for (int mt = 0; mt < 2; mt++)
        #pragma unroll
        for (int nt = 0; nt < 8; nt++)
            #pragma unroll
            for (int i = 0; i < 4; i++) acc[mt][nt][i] = 0.f;

    float av[8], bv[8];
    {
        const float* ap = A + (size_t)(bm + arow) * K + akq;
        float4 x = *(const float4*)ap;
        float4 y = *(const float4*)(ap + 4);
        av[0]=x.x; av[1]=x.y; av[2]=x.z; av[3]=x.w;
        av[4]=y.x; av[5]=y.y; av[6]=y.z; av[7]=y.w;
        const float* bp = B + (size_t)bkh * ldb + bn + bnn;
        #pragma unroll
        for (int j = 0; j < 8; j++) bv[j] = bp[(size_t)j * ldb];
    }
    cvt_store8(sm + arow * SSTR + akq, sm + A_LO + arow * SSTR + akq, av);
    cvt_store8(sm + B_HI + bnn * SSTR + bkh, sm + B_LO + bnn * SSTR + bkh, bv);
    __syncthreads();

    const int KT = K >> 4;
    for (int kt = 0; kt < KT; kt++) {
        const int cur = (kt & 1) ? STAGE_ELEMS : 0;

        if (kt + 1 < KT) {
            const int k0 = (kt + 1) << 4;
            const float* ap = A + (size_t)(bm + arow) * K + k0 + akq;
            float4 x = *(const float4*)ap;
            float4 y = *(const float4*)(ap + 4);
            av[0]=x.x; av[1]=x.y; av[2]=x.z; av[3]=x.w;
            av[4]=y.x; av[5]=y.y; av[6]=y.z; av[7]=y.w;
            const float* bp = B + (size_t)(k0 + bkh) * ldb + bn + bnn;
            #pragma unroll
            for (int j = 0; j < 8; j++) bv[j] = bp[(size_t)j * ldb];
        }

        const __nv_bfloat16* Ah = sm + cur;
        const __nv_bfloat16* Al = Ah + A_LO;
        const __nv_bfloat16* Bh = sm + cur + B_HI;
        const __nv_bfloat16* Bl = sm + cur + B_LO;

        uint32_t ah[2][4], al[2][4];
        #pragma unroll
        for (int mt = 0; mt < 2; mt++) {
            const int r = wm + mt * 16 + (lane & 15);
            const int co = (lane >> 4) * 8;
            ldsm_x4(ah[mt], smem_u32(Ah + r * SSTR + co));
            ldsm_x4(al[mt], smem_u32(Al + r * SSTR + co));
        }
        uint32_t bh[8][2], bl[8][2];
        #pragma unroll
        for (int pr = 0; pr < 4; pr++) {
            const int r  = wn + pr * 16 + (lane & 7) + ((lane & 16) >> 1);
            const int co = lane & 8;
            uint32_t t[4];
            ldsm_x4(t, smem_u32(Bh + r * SSTR + co));
            bh[2*pr][0]=t[0]; bh[2*pr][1]=t[1]; bh[2*pr+1][0]=t[2]; bh[2*pr+1][1]=t[3];
            ldsm_x4(t, smem_u32(Bl + r * SSTR + co));
            bl[2*pr][0]=t[0]; bl[2*pr][1]=t[1]; bl[2*pr+1][0]=t[2]; bl[2*pr+1][1]=t[3];
        }

        #pragma unroll
        for (int mt = 0; mt < 2; mt++)
            #pragma unroll
            for (int nt = 0; nt < 8; nt++) {
                mma16816(acc[mt][nt], ah[mt], bh[nt]);
                mma16816(acc[mt][nt], ah[mt], bl[nt]);
                mma16816(acc[mt][nt], al[mt], bh[nt]);
            }

        if (kt + 1 < KT) {
            const int nxt = (kt & 1) ? 0 : STAGE_ELEMS;
            cvt_store8(sm + nxt + arow * SSTR + akq,
                       sm + nxt + A_LO + arow * SSTR + akq, av);
            cvt_store8(sm + nxt + B_HI + bnn * SSTR + bkh,
                       sm + nxt + B_LO + bnn * SSTR + bkh, bv);
        }
        __syncthreads();
    }

    #pragma unroll
    for (int mt = 0; mt < 2; mt++) {
        const int r0 = bm + wm + mt * 16 + g;
        #pragma unroll
        for (int nt = 0; nt < 8; nt++) {
            const int c = bn + wn + nt * 8 + tg * 2;
            *(float2*)&C[(size_t)r0 * ldc + c] =
                make_float2(acc[mt][nt][0], acc[mt][nt][1]);
            *(float2*)&C[(size_t)(r0 + 8) * ldc + c] =
                make_float2(acc[mt][nt][2], acc[mt][nt][3]);
        }
    }
}

// ---------------- exact fp32 SGEMM (gate columns only) ----------------------
__global__ __launch_bounds__(256) void sgemm_kernel(
    const float* __restrict__ A, const float* __restrict__ B,
    float* __restrict__ C, int M, int N, int K, int ldb, int ldc)
{
    __shared__ float As[8][128];
    __shared__ float Bs[8][128];

    const int tid  = threadIdx.x;
    const int bm   = blockIdx.y * 128;
    const int bn   = blockIdx.x * 128;
    const int rowA = tid >> 1,  colA = (tid & 1) * 4;
    const int rowB = tid >> 5,  colB = (tid & 31) * 4;
    const int tr   = (tid >> 4) * 8;
    const int tc   = (tid & 15) * 8;

    float acc[8][8] = {};

    for (int k0 = 0; k0 < K; k0 += 8) {
        float4 a4 = *reinterpret_cast<const float4*>(
            A + (size_t)(bm + rowA) * K + k0 + colA);
        float4 b4 = make_float4(0.f, 0.f, 0.f, 0.f);
        if (bn + colB < N)
            b4 = *reinterpret_cast<const float4*>(
                B + (size_t)(k0 + rowB) * ldb + bn + colB);

        __syncthreads();
        As[colA + 0][rowA] = a4.x;
        As[colA + 1][rowA] = a4.y;
        As[colA + 2][rowA] = a4.z;
        As[colA + 3][rowA] = a4.w;
        *reinterpret_cast<float4*>(&Bs[rowB][colB]) = b4;
        __syncthreads();

        #pragma unroll
        for (int kk = 0; kk < 8; kk++) {
            float ar[8], br[8];
            *reinterpret_cast<float4*>(ar)     = *reinterpret_cast<const float4*>(&As[kk][tr]);
            *reinterpret_cast<float4*>(ar + 4) = *reinterpret_cast<const float4*>(&As[kk][tr + 4]);
            *reinterpret_cast<float4*>(br)     = *reinterpret_cast<const float4*>(&Bs[kk][tc]);
            *reinterpret_cast<float4*>(br + 4) = *reinterpret_cast<const float4*>(&Bs[kk][tc + 4]);
            #pragma unroll
            for (int i = 0; i < 8; i++)
                #pragma unroll
                for (int j = 0; j < 8; j++)
                    acc[i][j] = fmaf(ar[i], br[j], acc[i][j]);
        }
    }

    #pragma unroll
    for (int i = 0; i < 8; i++) {
        float* crow = C + (size_t)(bm + tr + i) * ldc + bn;
        #pragma unroll
        for (int j = 0; j < 8; j += 4) {
            if (bn + tc + j < N)
                *reinterpret_cast<float4*>(crow + tc + j) =
                    make_float4(acc[i][j], acc[i][j + 1], acc[i][j + 2], acc[i][j + 3]);
        }
    }
}

// ---------------- RMSNorm + RoPE + bf16 hi/lo split (q,k,v) ----------------
__global__ __launch_bounds__(256) void norm_rope_kernel(
    const float* __restrict__ qg, const float* __restrict__ kb,
    const float* __restrict__ vb,
    const float* __restrict__ qw, const float* __restrict__ kw,
    const int* __restrict__ positions,
    __nv_bfloat16* __restrict__ Qh, __nv_bfloat16* __restrict__ Ql,
    __nv_bfloat16* __restrict__ Kh, __nv_bfloat16* __restrict__ Kl,
    __nv_bfloat16* __restrict__ Vh, __nv_bfloat16* __restrict__ Vl)
{
    const int t   = blockIdx.x;
    const int tid = threadIdx.x;
    __shared__ float red[256];
    __shared__ float cs[64], sn[64];
    __shared__ float rq_s, rk_s;

    const float* qrow = qg + (size_t)t * NQG;
    const float* krow = kb + (size_t)t * HID;
    const float* vrow = vb + (size_t)t * HID;
    const float scale = 0.08838834764831843f;

    float sq = 0.f, sk = 0.f;
    for (int i = tid; i < HID; i += 256) {
        float a = qrow[i]; sq = fmaf(a, a, sq);
        float b = krow[i]; sk = fmaf(b, b, sk);
    }
    red[tid] = sq; __syncthreads();
    for (int s = 128; s > 0; s >>= 1) { if (tid < s) red[tid] += red[tid + s]; __syncthreads(); }
    if (tid == 0) rq_s = rsqrtf(red[0] * (1.f / (float)HID) + 1e-6f);
    __syncthreads();
    red[tid] = sk; __syncthreads();
    for (int s = 128; s > 0; s >>= 1) { if (tid < s) red[tid] += red[tid + s]; __syncthreads(); }
    if (tid == 0) rk_s = rsqrtf(red[0] * (1.f / (float)HID) + 1e-6f);

    if (tid < 64) {
        double invf = exp(-(double)tid * (log(500000.0) / 64.0));
        double ang  = (double)positions[t] * invf;
        double sd, cd;
        sincos(ang, &sd, &cd);
        cs[tid] = (float)cd;
        sn[tid] = (float)sd;
    }
    __syncthreads();

    const float rq = rq_s, rk = rk_s;
    for (int pid = tid; pid < NH * 64; pid += 256) {
        int hh = pid >> 6, j = pid & 63;
        int i1 = hh * HD + j, i2 = i1 + 64;
        float c = cs[j], s = sn[j];
        float x1 = qrow[i1] * rq * qw[i1];
        float x2 = qrow[i2] * rq * qw[i2];
        float q1 = (x1 * c - x2 * s) * scale;
        float q2 = (x2 * c + x1 * s) * scale;
        float y1 = krow[i1] * rk * kw[i1];
        float y2 = krow[i2] * rk * kw[i2];
        float k1 = y1 * c - y2 * s;
        float k2 = y2 * c + y1 * s;

        size_t b = (size_t)t * HID;
        __nv_bfloat16 h;
        h = __float2bfloat16(q1); Qh[b+i1] = h; Ql[b+i1] = __float2bfloat16(q1 - __bfloat162float(h));
        h = __float2bfloat16(q2); Qh[b+i2] = h; Ql[b+i2] = __float2bfloat16(q2 - __bfloat162float(h));
        h = __float2bfloat16(k1); Kh[b+i1] = h; Kl[b+i1] = __float2bfloat16(k1 - __bfloat162float(h));
        h = __float2bfloat16(k2); Kh[b+i2] = h; Kl[b+i2] = __float2bfloat16(k2 - __bfloat162float(h));
    }
    for (int i = tid; i < HID; i += 256) {
        float v = vrow[i];
        __nv_bfloat16 h = __float2bfloat16(v);
        size_t b = (size_t)t * HID + i;
        Vh[b] = h; Vl[b] = __float2bfloat16(v - __bfloat162float(h));
    }
}

// ============================================================================
// Fused-pass tensor-core dual attention with cp.async K/V ping-pong.
// One CTA = (head, 64-query block), 4 warps x 16 rows.
// Raw S computed ONCE per key tile; global softmax always, local softmax +
// second O accumulator only on the <=3 tiles intersecting the 128 window,
// reusing the same V fragments.  K(kt+1) prefetched during PV(kt); V(kt+1)
// prefetched during QK(kt+1).
// ============================================================================
#define BR 64
#define BC 64
#define ASTR 136
#define ATTN_SMEM (6 * BC * ASTR * 2)

__global__ __launch_bounds__(128, 2) void attn_mma_kernel(
    const __nv_bfloat16* __restrict__ Qh, const __nv_bfloat16* __restrict__ Ql,
    const __nv_bfloat16* __restrict__ Kh, const __nv_bfloat16* __restrict__ Kl,
    const __nv_bfloat16* __restrict__ Vh, const __nv_bfloat16* __restrict__ Vl,
    const float* __restrict__ qg, float* __restrict__ outp,
    const int* __restrict__ positions)
{
    extern __shared__ char smraw[];
    __nv_bfloat16* sQh = (__nv_bfloat16*)smraw;
    __nv_bfloat16* sQl = sQh + BR * ASTR;
    __nv_bfloat16* sKh = sQl + BR * ASTR;
    __nv_bfloat16* sKl = sKh + BC * ASTR;
    __nv_bfloat16* sVh = sKl + BC * ASTR;
    __nv_bfloat16* sVl = sVh + BC * ASTR;

    const int qb   = (int)gridDim.x - 1 - (int)blockIdx.x;  // heavy blocks first
    const int h    = blockIdx.y;
    const int tid  = threadIdx.x;
    const int warp = tid >> 5, lane = tid & 31;
    const int g = lane >> 2, tg = lane & 3;

    const int  row  = tid >> 1;
    const int  half = (tid & 1) * 64;
    const uint32_t dKh = smem_u32(sKh + row * ASTR + half);
    const uint32_t dKl = smem_u32(sKl + row * ASTR + half);
    const uint32_t dVh = smem_u32(sVh + row * ASTR + half);
    const uint32_t dVl = smem_u32(sVl + row * ASTR + half);

    // ---- prologue: Q + K(0) in group 0, V(0) in group 1
    {
        const size_t gq = (size_t)(qb * BR + row) * HID + h * HD + half;
        const uint32_t dQh = smem_u32(sQh + row * ASTR + half);
        const uint32_t dQl = smem_u32(sQl + row * ASTR + half);
        #pragma unroll
        for (int i = 0; i < 8; i++) {
            cpa16(dQh + i * 16, Qh + gq + i * 8);
            cpa16(dQl + i * 16, Ql + gq + i * 8);
        }
        const size_t gk = (size_t)row * HID + h * HD + half;   // kt = 0
        #pragma unroll
        for (int i = 0; i < 8; i++) {
            cpa16(dKh + i * 16, Kh + gk + i * 8);
            cpa16(dKl + i * 16, Kl + gk + i * 8);
        }
        cp_commit();
        #pragma unroll
        for (int i = 0; i < 8; i++) {
            cpa16(dVh + i * 16, Vh + gk + i * 8);
            cpa16(dVl + i * 16, Vl + gk + i * 8);
        }
        cp_commit();
    }

    const int qp0 = positions[qb * BR + warp * 16 + g];
    const int qp1 = positions[qb * BR + warp * 16 + g + 8];

    const uint32_t aQh = smem_u32(sQh + (warp * 16 + (lane & 15)) * ASTR + (lane >> 4) * 8);
    const uint32_t aQl = smem_u32(sQl + (warp * 16 + (lane & 15)) * ASTR + (lane >> 4) * 8);
    const int bKrow = (lane & 7) + ((lane & 16) >> 1);
    const int bKco  = lane & 8;
    const int vKrow = (lane & 8) + (lane & 7);
    const int vDco  = (lane & 16) >> 1;

    float mg0 = -1e30f, mg1 = -1e30f, lg0 = 0.f, lg1 = 0.f;
    float ml0 = -1e30f, ml1 = -1e30f, ll0 = 0.f, ll1 = 0.f;
    float og[16][4], ol[16][4];
    #pragma unroll
    for (int nt = 0; nt < 16; nt++)
        #pragma unroll
        for (int i = 0; i < 4; i++) { og[nt][i] = 0.f; ol[nt][i] = 0.f; }

    cp_wait1();            // Q + K(0) ready (V(0) may be in flight)
    __syncthreads();

    for (int kt = 0; kt <= qb; kt++) {
        // ================= S = Q K^T (bf16x3), reads sK =================
        float s[8][4];
        #pragma unroll
        for (int nt = 0; nt < 8; nt++)
            #pragma unroll
            for (int i = 0; i < 4; i++) s[nt][i] = 0.f;

        #pragma unroll
        for (int kk = 0; kk < 8; kk++) {
            uint32_t ah[4], al[4];
            ldsm_x4(ah, aQh + kk * 32);
            ldsm_x4(al, aQl + kk * 32);
            uint32_t bh[8][2], bl[8][2];
            #pragma unroll
            for (int pr = 0; pr < 4; pr++) {
                const int r = pr * 16 + bKrow;
                uint32_t t4[4];
                ldsm_x4(t4, smem_u32(sKh + r * ASTR + kk * 16 + bKco));
                bh[2*pr][0]=t4[0]; bh[2*pr][1]=t4[1]; bh[2*pr+1][0]=t4[2]; bh[2*pr+1][1]=t4[3];
                ldsm_x4(t4, smem_u32(sKl + r * ASTR + kk * 16 + bKco));
                bl[2*pr][0]=t4[0]; bl[2*pr][1]=t4[1]; bl[2*pr+1][0]=t4[2]; bl[2*pr+1][1]=t4[3];
            }
            #pragma unroll
            for (int nt = 0; nt < 8; nt++) {
                mma16816(s[nt], ah, bh[nt]);
                mma16816(s[nt], ah, bl[nt]);
                mma16816(s[nt], al, bh[nt]);
            }
        }

        __syncthreads();                 // all warps done reading sK
        if (kt < qb) {                   // prefetch K(kt+1)
            const size_t gk = (size_t)((kt + 1) * BC + row) * HID + h * HD + half;
            #pragma unroll
            for (int i = 0; i < 8; i++) {
                cpa16(dKh + i * 16, Kh + gk + i * 8);
                cpa16(dKl + i * 16, Kl + gk + i * 8);
            }
        }
        cp_commit();
        cp_wait1();                      // V(kt) complete
        __syncthreads();

        // ================= masks + dual online softmax =================
        const bool diag = (kt == qb);
        const bool loct = (kt >= qb - 2);

        int kp[16];
        if (diag || loct) {
            #pragma unroll
            for (int nt = 0; nt < 8; nt++) {
                kp[2*nt]   = positions[kt * BC + 8 * nt + 2 * tg];
                kp[2*nt+1] = positions[kt * BC + 8 * nt + 2 * tg + 1];
            }
        }
        if (diag) {
            #pragma unroll
            for (int nt = 0; nt < 8; nt++)
                #pragma unroll
                for (int j = 0; j < 2; j++) {
                    if (qp0 < kp[2*nt+j]) s[nt][j]     = -1e30f;
                    if (qp1 < kp[2*nt+j]) s[nt][2 + j] = -1e30f;
                }
        }

        // global row maxes
        float mx0 = -1e30f, mx1 = -1e30f;
        #pragma unroll
        for (int nt = 0; nt < 8; nt++) {
            mx0 = fmaxf(mx0, fmaxf(s[nt][0], s[nt][1]));
            mx1 = fmaxf(mx1, fmaxf(s[nt][2], s[nt][3]));
        }
        mx0 = fmaxf(mx0, __shfl_xor_sync(0xffffffffu, mx0, 1));
        mx0 = fmaxf(mx0, __shfl_xor_sync(0xffffffffu, mx0, 2));
        mx1 = fmaxf(mx1, __shfl_xor_sync(0xffffffffu, mx1, 1));
        mx1 = fmaxf(mx1, __shfl_xor_sync(0xffffffffu, mx1, 2));

        const float mng0 = fmaxf(fmaxf(mg0, mx0), -1e28f);
        const float mng1 = fmaxf(fmaxf(mg1, mx1), -1e28f);
        const float alg0 = __expf(mg0 - mng0);
        const float alg1 = __expf(mg1 - mng1);

        // local masks + maxes
        uint32_t lmask = 0;
        float mnl0 = 0.f, mnl1 = 0.f, all0 = 0.f, all1 = 0.f;
        if (loct) {
            float mxl0 = -1e30f, mxl1 = -1e30f;
            #pragma unroll
            for (int nt = 0; nt < 8; nt++)
                #pragma unroll
                for (int j = 0; j < 2; j++) {
                    const int kpv = kp[2*nt+j];
                    if (qp0 >= kpv && qp0 - kpv < WIN) {
                        mxl0 = fmaxf(mxl0, s[nt][j]);
                        lmask |= 1u << (nt * 4 + j);
                    }
                    if (qp1 >= kpv && qp1 - kpv < WIN) {
                        mxl1 = fmaxf(mxl1, s[nt][2 + j]);
                        lmask |= 1u << (nt * 4 + 2 + j);
                    }
                }
            mxl0 = fmaxf(mxl0, __shfl_xor_sync(0xffffffffu, mxl0, 1));
            mxl0 = fmaxf(mxl0, __shfl_xor_sync(0xffffffffu, mxl0, 2));
            mxl1 = fmaxf(mxl1, __shfl_xor_sync(0xffffffffu, mxl1, 1));
            mxl1 = fmaxf(mxl1, __shfl_xor_sync(0xffffffffu, mxl1, 2));
            mnl0 = fmaxf(fmaxf(ml0, mxl0), -1e28f);
            mnl1 = fmaxf(fmaxf(ml1, mxl1), -1e28f);
            all0 = __expf(ml0 - mnl0);
            all1 = __expf(ml1 - mnl1);
        }

        // exponentiate (global in place; local into pl)
        float pl[8][4];
        float sg0 = 0.f, sg1 = 0.f, sl0 = 0.f, sl1 = 0.f;
        #pragma unroll
        for (int nt = 0; nt < 8; nt++) {
            #pragma unroll
            for (int j = 0; j < 2; j++) {
                float v0 = s[nt][j], v1 = s[nt][2 + j];
                float p0 = __expf(v0 - mng0); s[nt][j]     = p0; sg0 += p0;
                float p1 = __expf(v1 - mng1); s[nt][2 + j] = p1; sg1 += p1;
                if (loct) {
                    float q0 = (lmask >> (nt * 4 + j)) & 1u ? __expf(v0 - mnl0) : 0.f;
                    float q1 = (lmask >> (nt * 4 + 2 + j)) & 1u ? __expf(v1 - mnl1) : 0.f;
                    pl[nt][j] = q0;     sl0 += q0;
                    pl[nt][2 + j] = q1; sl1 += q1;
                }
            }
        }
        sg0 += __shfl_xor_sync(0xffffffffu, sg0, 1);
        sg0 += __shfl_xor_sync(0xffffffffu, sg0, 2);
        sg1 += __shfl_xor_sync(0xffffffffu, sg1, 1);
        sg1 += __shfl_xor_sync(0xffffffffu, sg1, 2);
        lg0 = lg0 * alg0 + sg0; mg0 = mng0;
        lg1 = lg1 * alg1 + sg1; mg1 = mng1;
        #pragma unroll
        for (int nt = 0; nt < 16; nt++) {
            og[nt][0] *= alg0; og[nt][1] *= alg0;
            og[nt][2] *= alg1; og[nt][3] *= alg1;
        }
        if (loct) {
            sl0 += __shfl_xor_sync(0xffffffffu, sl0, 1);
            sl0 += __shfl_xor_sync(0xffffffffu, sl0, 2);
            sl1 += __shfl_xor_sync(0xffffffffu, sl1, 1);
            sl1 += __shfl_xor_sync(0xffffffffu, sl1, 2);
            ll0 = ll0 * all0 + sl0; ml0 = mnl0;
            ll1 = ll1 * all1 + sl1; ml1 = mnl1;
            #pragma unroll
            for (int nt = 0; nt < 16; nt++) {
                ol[nt][0] *= all0; ol[nt][1] *= all0;
                ol[nt][2] *= all1; ol[nt][3] *= all1;
            }
        }

        // ================= O += P V (shared V fragments) =================
        #pragma unroll
        for (int kk = 0; kk < 4; kk++) {
            uint32_t ghi[4], glo[4], lhi[4], llo[4];
            split2(s[2*kk][0],   s[2*kk][1],   ghi[0], glo[0]);
            split2(s[2*kk][2],   s[2*kk][3],   ghi[1], glo[1]);
            split2(s[2*kk+1][0], s[2*kk+1][1], ghi[2], glo[2]);
            split2(s[2*kk+1][2], s[2*kk+1][3], ghi[3], glo[3]);
            if (loct) {
                split2(pl[2*kk][0],   pl[2*kk][1],   lhi[0], llo[0]);
                split2(pl[2*kk][2],   pl[2*kk][3],   lhi[1], llo[1]);
                split2(pl[2*kk+1][0], pl[2*kk+1][1], lhi[2], llo[2]);
                split2(pl[2*kk+1][2], pl[2*kk+1][3], lhi[3], llo[3]);
            }
            #pragma unroll
            for (int dn = 0; dn < 8; dn++) {
                uint32_t vh4[4], vl4[4];
                ldsm_x4_t(vh4, smem_u32(sVh + (kk * 16 + vKrow) * ASTR + dn * 16 + vDco));
                ldsm_x4_t(vl4, smem_u32(sVl + (kk * 16 + vKrow) * ASTR + dn * 16 + vDco));
                mma16816(og[2*dn],     ghi, &vh4[0]);
                mma16816(og[2*dn + 1], ghi, &vh4[2]);
                mma16816(og[2*dn],     glo, &vh4[0]);
                mma16816(og[2*dn + 1], glo, &vh4[2]);
                mma16816(og[2*dn],     ghi, &vl4[0]);
                mma16816(og[2*dn + 1], ghi, &vl4[2]);
                if (loct) {
                    mma16816(ol[2*dn],     lhi, &vh4[0]);
                    mma16816(ol[2*dn + 1], lhi, &vh4[2]);
                    mma16816(ol[2*dn],     llo, &vh4[0]);
                    mma16816(ol[2*dn + 1], llo, &vh4[2]);
                    mma16816(ol[2*dn],     lhi, &vl4[0]);
                    mma16816(ol[2*dn + 1], lhi, &vl4[2]);
                }
            }
        }

        __syncthreads();                 // all warps done reading sV
        if (kt < qb) {                   // prefetch V(kt+1)
            const size_t gk = (size_t)((kt + 1) * BC + row) * HID + h * HD + half;
            #pragma unroll
            for (int i = 0; i < 8; i++) {
                cpa16(dVh + i * 16, Vh + gk + i * 8);
                cpa16(dVl + i * 16, Vl + gk + i * 8);
            }
        }
        cp_commit();
        cp_wait1();                      // K(kt+1) complete
        __syncthreads();
    }

    // ================= epilogue: gate selects accumulator =================
    const int t0 = qb * BR + warp * 16 + g;
    const bool u0 = qg[(size_t)t0 * NQG + NH * HD + h] > 0.f;
    const bool u1 = qg[(size_t)(t0 + 8) * NQG + NH * HD + h] > 0.f;
    const float inv0 = 1.f / (u0 ? lg0 : ll0);
    const float inv1 = 1.f / (u1 ? lg1 : ll1);
    #pragma unroll
    for (int nt = 0; nt < 16; nt++) {
        const int d = 8 * nt + 2 * tg;
        float a0 = (u0 ? og[nt][0] : ol[nt][0]) * inv0;
        float b0 = (u0 ? og[nt][1] : ol[nt][1]) * inv0;
        float a1 = (u1 ? og[nt][2] : ol[nt][2]) * inv1;
        float b1 = (u1 ? og[nt][3] : ol[nt][3]) * inv1;
        *(float2*)&outp[(size_t)t0 * HID + h * HD + d]       = make_float2(a0, b0);
        *(float2*)&outp[(size_t)(t0 + 8) * HID + h * HD + d] = make_float2(a1, b1);
    }
}

// ---------------------------------------------------------------------------
extern "C" void kernel_launch(void* const* d_in, const int* in_sizes, int n_in,
                              void* d_out, int out_size)
{
    const float* X   = (const float*)d_in[0];
    const int*   pos = (const int*)  d_in[1];
    const float* Wq  = (const float*)d_in[2];
    const float* Wk  = (const float*)d_in[3];
    const float* Wv  = (const float*)d_in[4];
    const float* Wo  = (const float*)d_in[5];
    const float* qw  = (const float*)d_in[6];
    const float* kw  = (const float*)d_in[7];
    float* out = (float*)d_out;

    float *qg, *kb, *vb, *bl;
    __nv_bfloat16 *Qh, *Ql, *Kh, *Kl, *Vh, *Vl;
    cudaGetSymbolAddress((void**)&qg, d_qg);
    cudaGetSymbolAddress((void**)&kb, d_kbuf);
    cudaGetSymbolAddress((void**)&vb, d_vbuf);
    cudaGetSymbolAddress((void**)&bl, d_blend);
    cudaGetSymbolAddress((void**)&Qh, d_Qh);
    cudaGetSymbolAddress((void**)&Ql, d_Ql);
    cudaGetSymbolAddress((void**)&Kh, d_Kh);
    cudaGetSymbolAddress((void**)&Kl, d_Kl);
    cudaGetSymbolAddress((void**)&Vh, d_Vh);
    cudaGetSymbolAddress((void**)&Vl, d_Vl);

    cudaFuncSetAttribute(mma_gemm, cudaFuncAttributeMaxDynamicSharedMemorySize,
                         GEMM_SMEM);
    cudaFuncSetAttribute(attn_mma_kernel, cudaFuncAttributeMaxDynamicSharedMemorySize,
                         ATTN_SMEM);

    dim3 blk(256);
    dim3 gtile(16, 16);

    mma_gemm<<<gtile, blk, GEMM_SMEM>>>(X, Wq, qg, HID, NQG, NQG);
    sgemm_kernel<<<dim3(1, 16), blk>>>(X, Wq + NH * HD, qg + NH * HD,
                                       T_TOK, NH, HID, NQG, NQG);
    mma_gemm<<<gtile, blk, GEMM_SMEM>>>(X, Wk, kb, HID, HID, HID);
    mma_gemm<<<gtile, blk, GEMM_SMEM>>>(X, Wv, vb, HID, HID, HID);

    norm_rope_kernel<<<T_TOK, 256>>>(qg, kb, vb, qw, kw, pos,
                                     Qh, Ql, Kh, Kl, Vh, Vl);

    dim3 ga(T_TOK / BR, NH);   // 32 x 16
    attn_mma_kernel<<<ga, 128, ATTN_SMEM>>>(Qh, Ql, Kh, Kl, Vh, Vl,
                                            qg, bl, pos);

    mma_gemm<<<gtile, blk, GEMM_SMEM>>>(bl, Wo, out, HID, HID, HID);
}

// round 11
// speedup vs baseline: 2.2756x; 1.1220x over previous
#include <cuda_runtime.h>
#include <cuda_bf16.h>
#include <cuda_fp16.h>
#include <math.h>
#include <stdint.h>

#define T_TOK 2048
#define HID   2048
#define NH    16
#define HD    128
#define NQG   2064      // H*D + H
#define WIN   128

// ---------------- scratch (static device globals; no runtime allocation) ----
__device__ float d_qg[T_TOK * NQG];     // X @ Wq  (gate cols 2048..2063)
__device__ float d_kbuf[T_TOK * HID];   // X @ Wk (pre-norm)
__device__ float d_vbuf[T_TOK * HID];   // X @ Wv
__device__ float d_blend[T_TOK * HID];  // gated attention output

__device__ __nv_bfloat16 d_Qh[T_TOK * HID];
__device__ __nv_bfloat16 d_Ql[T_TOK * HID];
__device__ __nv_bfloat16 d_Kh[T_TOK * HID];
__device__ __nv_bfloat16 d_Kl[T_TOK * HID];
__device__ __half        d_Vf[T_TOK * HID];

// ---------------- common helpers -------------------------------------------
__device__ __forceinline__ uint32_t smem_u32(const void* p) {
    return (uint32_t)__cvta_generic_to_shared(p);
}
__device__ __forceinline__ void ldsm_x4(uint32_t* r, uint32_t addr) {
    asm volatile("ldmatrix.sync.aligned.m8n8.x4.shared.b16 {%0,%1,%2,%3}, [%4];\n"
        : "=r"(r[0]), "=r"(r[1]), "=r"(r[2]), "=r"(r[3]) : "r"(addr));
}
__device__ __forceinline__ void ldsm_x4_t(uint32_t* r, uint32_t addr) {
    asm volatile("ldmatrix.sync.aligned.m8n8.x4.trans.shared.b16 {%0,%1,%2,%3}, [%4];\n"
        : "=r"(r[0]), "=r"(r[1]), "=r"(r[2]), "=r"(r[3]) : "r"(addr));
}
__device__ __forceinline__ void mma16816(float* d, const uint32_t* a, const uint32_t* b) {
    asm volatile(
        "mma.sync.aligned.m16n8k16.row.col.f32.bf16.bf16.f32 "
        "{%0,%1,%2,%3}, {%4,%5,%6,%7}, {%8,%9}, {%0,%1,%2,%3};\n"
        : "+f"(d[0]), "+f"(d[1]), "+f"(d[2]), "+f"(d[3])
        : "r"(a[0]), "r"(a[1]), "r"(a[2]), "r"(a[3]), "r"(b[0]), "r"(b[1]));
}
__device__ __forceinline__ void mma16816h(float* d, const uint32_t* a, const uint32_t* b) {
    asm volatile(
        "mma.sync.aligned.m16n8k16.row.col.f32.f16.f16.f32 "
        "{%0,%1,%2,%3}, {%4,%5,%6,%7}, {%8,%9}, {%0,%1,%2,%3};\n"
        : "+f"(d[0]), "+f"(d[1]), "+f"(d[2]), "+f"(d[3])
        : "r"(a[0]), "r"(a[1]), "r"(a[2]), "r"(a[3]), "r"(b[0]), "r"(b[1]));
}
__device__ __forceinline__ uint32_t packh2(float a, float b) {
    __half2 h = __floats2half2_rn(a, b);
    return *(uint32_t*)&h;
}
__device__ __forceinline__ float ex2(float x) {
    float y;
    asm("ex2.approx.ftz.f32 %0, %1;" : "=f"(y) : "f"(x));
    return y;
}
__device__ __forceinline__ void cvt_store8(__nv_bfloat16* hi, __nv_bfloat16* lo,
                                           const float* v) {
    union { __nv_bfloat16 b[8]; uint4 u; } ph, pl;
    #pragma unroll
    for (int j = 0; j < 8; j++) {
        __nv_bfloat16 h = __float2bfloat16(v[j]);
        ph.b[j] = h;
        pl.b[j] = __float2bfloat16(v[j] - __bfloat162float(h));
    }
    *(uint4*)hi = ph.u;
    *(uint4*)lo = pl.u;
}
__device__ __forceinline__ void cpa16(uint32_t dst, const void* src) {
    asm volatile("cp.async.cg.shared.global [%0], [%1], 16;\n" :: "r"(dst), "l"(src));
}
__device__ __forceinline__ void cp_commit() {
    asm volatile("cp.async.commit_group;\n" ::: "memory");
}
__device__ __forceinline__ void cp_wait1() {
    asm volatile("cp.async.wait_group 1;\n" ::: "memory");
}

// ============================================================================
// bf16x3 tensor-core GEMM (fp32 in/out), 128x128 tile, BK=16, 256 threads.
// ============================================================================
#define SSTR 24
#define STAGE_ELEMS (4 * 128 * SSTR)
#define GEMM_SMEM (2 * STAGE_ELEMS * 2)

__global__ __launch_bounds__(256, 2) void mma_gemm(
    const float* __restrict__ A, const float* __restrict__ B,
    float* __restrict__ C, int K, int ldb, int ldc)
{
    extern __shared__ char smraw[];
    __nv_bfloat16* sm = (__nv_bfloat16*)smraw;

    const int tid  = threadIdx.x;
    const int warp = tid >> 5, lane = tid & 31;
    const int bm   = blockIdx.y * 128, bn = blockIdx.x * 128;

    const int A_LO = 128 * SSTR;
    const int B_HI = 2 * 128 * SSTR;
    const int B_LO = 3 * 128 * SSTR;

    const int arow = tid >> 1;
    const int akq  = (tid & 1) * 8;
    const int bnn  = tid & 127;
    const int bkh  = (tid >> 7) * 8;

    const int wm = (warp & 3) * 32;
    const int wn = (warp >> 2) * 64;
    const int g  = lane >> 2, tg = lane & 3;

    float acc[2][8][4];
    #pragma unroll
    for (int mt = 0; mt < 2; mt++)
        #pragma unroll
        for (int nt = 0; nt < 8; nt++)
            #pragma unroll
            for (int i = 0; i < 4; i++) acc[mt][nt][i] = 0.f;

    float av[8], bv[8];
    {
        const float* ap = A + (size_t)(bm + arow) * K + akq;
        float4 x = *(const float4*)ap;
        float4 y = *(const float4*)(ap + 4);
        av[0]=x.x; av[1]=x.y; av[2]=x.z; av[3]=x.w;
        av[4]=y.x; av[5]=y.y; av[6]=y.z; av[7]=y.w;
        const float* bp = B + (size_t)bkh * ldb + bn + bnn;
        #pragma unroll
        for (int j = 0; j < 8; j++) bv[j] = bp[(size_t)j * ldb];
    }
    cvt_store8(sm + arow * SSTR + akq, sm + A_LO + arow * SSTR + akq, av);
    cvt_store8(sm + B_HI + bnn * SSTR + bkh, sm + B_LO + bnn * SSTR + bkh, bv);
    __syncthreads();

    const int KT = K >> 4;
    for (int kt = 0; kt < KT; kt++) {
        const int cur = (kt & 1) ? STAGE_ELEMS : 0;

        if (kt + 1 < KT) {
            const int k0 = (kt + 1) << 4;
            const float* ap = A + (size_t)(bm + arow) * K + k0 + akq;
            float4 x = *(const float4*)ap;
            float4 y = *(const float4*)(ap + 4);
            av[0]=x.x; av[1]=x.y; av[2]=x.z; av[3]=x.w;
            av[4]=y.x; av[5]=y.y; av[6]=y.z; av[7]=y.w;
            const float* bp = B + (size_t)(k0 + bkh) * ldb + bn + bnn;
            #pragma unroll
            for (int j = 0; j < 8; j++) bv[j] = bp[(size_t)j * ldb];
        }

        const __nv_bfloat16* Ah = sm + cur;
        const __nv_bfloat16* Al = Ah + A_LO;
        const __nv_bfloat16* Bh = sm + cur + B_HI;
        const __nv_bfloat16* Bl = sm + cur + B_LO;

        uint32_t ah[2][4], al[2][4];
        #pragma unroll
        for (int mt = 0; mt < 2; mt++) {
            const int r = wm + mt * 16 + (lane & 15);
            const int co = (lane >> 4) * 8;
            ldsm_x4(ah[mt], smem_u32(Ah + r * SSTR + co));
            ldsm_x4(al[mt], smem_u32(Al + r * SSTR + co));
        }
        uint32_t bh[8][2], bl[8][2];
        #pragma unroll
        for (int pr = 0; pr < 4; pr++) {
            const int r  = wn + pr * 16 + (lane & 7) + ((lane & 16) >> 1);
            const int co = lane & 8;
            uint32_t t[4];
            ldsm_x4(t, smem_u32(Bh + r * SSTR + co));
            bh[2*pr][0]=t[0]; bh[2*pr][1]=t[1]; bh[2*pr+1][0]=t[2]; bh[2*pr+1][1]=t[3];
            ldsm_x4(t, smem_u32(Bl + r * SSTR + co));
            bl[2*pr][0]=t[0]; bl[2*pr][1]=t[1]; bl[2*pr+1][0]=t[2]; bl[2*pr+1][1]=t[3];
        }

        #pragma unroll
        for (int mt = 0; mt < 2; mt++)
            #pragma unroll
            for (int nt = 0; nt < 8; nt++) {
                mma16816(acc[mt][nt], ah[mt], bh[nt]);
                mma16816(acc[mt][nt], ah[mt], bl[nt]);
                mma16816(acc[mt][nt], al[mt], bh[nt]);
            }

        if (kt + 1 < KT) {
            const int nxt = (kt & 1) ? 0 : STAGE_ELEMS;
            cvt_store8(sm + nxt + arow * SSTR + akq,
                       sm + nxt + A_LO + arow * SSTR + akq, av);
            cvt_store8(sm + nxt + B_HI + bnn * SSTR + bkh,
                       sm + nxt + B_LO + bnn * SSTR + bkh, bv);
        }
        __syncthreads();
    }

    #pragma unroll
    for (int mt = 0; mt < 2; mt++) {
        const int r0 = bm + wm + mt * 16 + g;
        #pragma unroll
        for (int nt = 0; nt < 8; nt++) {
            const int c = bn + wn + nt * 8 + tg * 2;
            *(float2*)&C[(size_t)r0 * ldc + c] =
                make_float2(acc[mt][nt][0], acc[mt][nt][1]);
            *(float2*)&C[(size_t)(r0 + 8) * ldc + c] =
                make_float2(acc[mt][nt][2], acc[mt][nt][3]);
        }
    }
}

// ---------------- exact fp32 SGEMM (gate columns only) ----------------------
__global__ __launch_bounds__(256) void sgemm_kernel(
    const float* __restrict__ A, const float* __restrict__ B,
    float* __restrict__ C, int M, int N, int K, int ldb, int ldc)
{
    __shared__ float As[8][128];
    __shared__ float Bs[8][128];

    const int tid  = threadIdx.x;
    const int bm   = blockIdx.y * 128;
    const int bn   = blockIdx.x * 128;
    const int rowA = tid >> 1,  colA = (tid & 1) * 4;
    const int rowB = tid >> 5,  colB = (tid & 31) * 4;
    const int tr   = (tid >> 4) * 8;
    const int tc   = (tid & 15) * 8;

    float acc[8][8] = {};

    for (int k0 = 0; k0 < K; k0 += 8) {
        float4 a4 = *reinterpret_cast<const float4*>(
            A + (size_t)(bm + rowA) * K + k0 + colA);
        float4 b4 = make_float4(0.f, 0.f, 0.f, 0.f);
        if (bn + colB < N)
            b4 = *reinterpret_cast<const float4*>(
                B + (size_t)(k0 + rowB) * ldb + bn + colB);

        __syncthreads();
        As[colA + 0][rowA] = a4.x;
        As[colA + 1][rowA] = a4.y;
        As[colA + 2][rowA] = a4.z;
        As[colA + 3][rowA] = a4.w;
        *reinterpret_cast<float4*>(&Bs[rowB][colB]) = b4;
        __syncthreads();

        #pragma unroll
        for (int kk = 0; kk < 8; kk++) {
            float ar[8], br[8];
            *reinterpret_cast<float4*>(ar)     = *reinterpret_cast<const float4*>(&As[kk][tr]);
            *reinterpret_cast<float4*>(ar + 4) = *reinterpret_cast<const float4*>(&As[kk][tr + 4]);
            *reinterpret_cast<float4*>(br)     = *reinterpret_cast<const float4*>(&Bs[kk][tc]);
            *reinterpret_cast<float4*>(br + 4) = *reinterpret_cast<const float4*>(&Bs[kk][tc + 4]);
            #pragma unroll
            for (int i = 0; i < 8; i++)
                #pragma unroll
                for (int j = 0; j < 8; j++)
                    acc[i][j] = fmaf(ar[i], br[j], acc[i][j]);
        }
    }

    #pragma unroll
    for (int i = 0; i < 8; i++) {
        float* crow = C + (size_t)(bm + tr + i) * ldc + bn;
        #pragma unroll
        for (int j = 0; j < 8; j += 4) {
            if (bn + tc + j < N)
                *reinterpret_cast<float4*>(crow + tc + j) =
                    make_float4(acc[i][j], acc[i][j + 1], acc[i][j + 2], acc[i][j + 3]);
        }
    }
}

// ---------------- RMSNorm + RoPE + bf16 hi/lo split (q,k), fp16 v ----------
// Q scale includes softmax scale AND log2(e) so attention works in exp2 domain.
__global__ __launch_bounds__(256) void norm_rope_kernel(
    const float* __restrict__ qg, const float* __restrict__ kb,
    const float* __restrict__ vb,
    const float* __restrict__ qw, const float* __restrict__ kw,
    const int* __restrict__ positions,
    __nv_bfloat16* __restrict__ Qh, __nv_bfloat16* __restrict__ Ql,
    __nv_bfloat16* __restrict__ Kh, __nv_bfloat16* __restrict__ Kl,
    __half* __restrict__ Vf)
{
    const int t   = blockIdx.x;
    const int tid = threadIdx.x;
    __shared__ float red[256];
    __shared__ float cs[64], sn[64];
    __shared__ float rq_s, rk_s;

    const float* qrow = qg + (size_t)t * NQG;
    const float* krow = kb + (size_t)t * HID;
    const float* vrow = vb + (size_t)t * HID;
    const float scale = 0.08838834764831843f * 1.4426950408889634f;

    float sq = 0.f, sk = 0.f;
    for (int i = tid; i < HID; i += 256) {
        float a = qrow[i]; sq = fmaf(a, a, sq);
        float b = krow[i]; sk = fmaf(b, b, sk);
    }
    red[tid] = sq; __syncthreads();
    for (int s = 128; s > 0; s >>= 1) { if (tid < s) red[tid] += red[tid + s]; __syncthreads(); }
    if (tid == 0) rq_s = rsqrtf(red[0] * (1.f / (float)HID) + 1e-6f);
    __syncthreads();
    red[tid] = sk; __syncthreads();
    for (int s = 128; s > 0; s >>= 1) { if (tid < s) red[tid] += red[tid + s]; __syncthreads(); }
    if (tid == 0) rk_s = rsqrtf(red[0] * (1.f / (float)HID) + 1e-6f);

    if (tid < 64) {
        double invf = exp(-(double)tid * (log(500000.0) / 64.0));
        double ang  = (double)positions[t] * invf;
        double sd, cd;
        sincos(ang, &sd, &cd);
        cs[tid] = (float)cd;
        sn[tid] = (float)sd;
    }
    __syncthreads();

    const float rq = rq_s, rk = rk_s;
    for (int pid = tid; pid < NH * 64; pid += 256) {
        int hh = pid >> 6, j = pid & 63;
        int i1 = hh * HD + j, i2 = i1 + 64;
        float c = cs[j], s = sn[j];
        float x1 = qrow[i1] * rq * qw[i1];
        float x2 = qrow[i2] * rq * qw[i2];
        float q1 = (x1 * c - x2 * s) * scale;
        float q2 = (x2 * c + x1 * s) * scale;
        float y1 = krow[i1] * rk * kw[i1];
        float y2 = krow[i2] * rk * kw[i2];
        float k1 = y1 * c - y2 * s;
        float k2 = y2 * c + y1 * s;

        size_t b = (size_t)t * HID;
        __nv_bfloat16 h;
        h = __float2bfloat16(q1); Qh[b+i1] = h; Ql[b+i1] = __float2bfloat16(q1 - __bfloat162float(h));
        h = __float2bfloat16(q2); Qh[b+i2] = h; Ql[b+i2] = __float2bfloat16(q2 - __bfloat162float(h));
        h = __float2bfloat16(k1); Kh[b+i1] = h; Kl[b+i1] = __float2bfloat16(k1 - __bfloat162float(h));
        h = __float2bfloat16(k2); Kh[b+i2] = h; Kl[b+i2] = __float2bfloat16(k2 - __bfloat162float(h));
    }
    for (int i = tid; i < HID; i += 256) {
        size_t b = (size_t)t * HID + i;
        Vf[b] = __float2half_rn(vrow[i]);
    }
}

// ============================================================================
// Fused-pass tensor-core dual attention, cp.async K/V ping-pong.
// QK^T: bf16x3.  PV: single-pass fp16 (P fp16 x V fp16, fp32 accumulate).
// exp via ex2.approx (log2e folded into Q scale).
// ============================================================================
#define BR 64
#define BC 64
#define ASTR 136
#define ATTN_SMEM (5 * BC * ASTR * 2)

__global__ __launch_bounds__(128, 2) void attn_mma_kernel(
    const __nv_bfloat16* __restrict__ Qh, const __nv_bfloat16* __restrict__ Ql,
    const __nv_bfloat16* __restrict__ Kh, const __nv_bfloat16* __restrict__ Kl,
    const __half* __restrict__ Vf,
    const float* __restrict__ qg, float* __restrict__ outp,
    const int* __restrict__ positions)
{
    extern __shared__ char smraw[];
    __nv_bfloat16* sQh = (__nv_bfloat16*)smraw;
    __nv_bfloat16* sQl = sQh + BR * ASTR;
    __nv_bfloat16* sKh = sQl + BR * ASTR;
    __nv_bfloat16* sKl = sKh + BC * ASTR;
    __half*        sVf = (__half*)(sKl + BC * ASTR);

    const int qb   = (int)gridDim.x - 1 - (int)blockIdx.x;  // heavy blocks first
    const int h    = blockIdx.y;
    const int tid  = threadIdx.x;
    const int warp = tid >> 5, lane = tid & 31;
    const int g = lane >> 2, tg = lane & 3;

    const int  row  = tid >> 1;
    const int  half = (tid & 1) * 64;
    const uint32_t dKh = smem_u32(sKh + row * ASTR + half);
    const uint32_t dKl = smem_u32(sKl + row * ASTR + half);
    const uint32_t dVf = smem_u32(sVf + row * ASTR + half);

    // ---- prologue: Q + K(0) in group 0, V(0) in group 1
    {
        const size_t gq = (size_t)(qb * BR + row) * HID + h * HD + half;
        const uint32_t dQh = smem_u32(sQh + row * ASTR + half);
        const uint32_t dQl = smem_u32(sQl + row * ASTR + half);
        #pragma unroll
        for (int i = 0; i < 8; i++) {
            cpa16(dQh + i * 16, Qh + gq + i * 8);
            cpa16(dQl + i * 16, Ql + gq + i * 8);
        }
        const size_t gk = (size_t)row * HID + h * HD + half;
        #pragma unroll
        for (int i = 0; i < 8; i++) {
            cpa16(dKh + i * 16, Kh + gk + i * 8);
            cpa16(dKl + i * 16, Kl + gk + i * 8);
        }
        cp_commit();
        #pragma unroll
        for (int i = 0; i < 8; i++)
            cpa16(dVf + i * 16, Vf + gk + i * 8);
        cp_commit();
    }

    const int qp0 = positions[qb * BR + warp * 16 + g];
    const int qp1 = positions[qb * BR + warp * 16 + g + 8];

    const uint32_t aQh = smem_u32(sQh + (warp * 16 + (lane & 15)) * ASTR + (lane >> 4) * 8);
    const uint32_t aQl = smem_u32(sQl + (warp * 16 + (lane & 15)) * ASTR + (lane >> 4) * 8);
    const int bKrow = (lane & 7) + ((lane & 16) >> 1);
    const int bKco  = lane & 8;
    const int vKrow = (lane & 8) + (lane & 7);
    const int vDco  = (lane & 16) >> 1;

    float mg0 = -1e30f, mg1 = -1e30f, lg0 = 0.f, lg1 = 0.f;
    float ml0 = -1e30f, ml1 = -1e30f, ll0 = 0.f, ll1 = 0.f;
    float og[16][4], ol[16][4];
    #pragma unroll
    for (int nt = 0; nt < 16; nt++)
        #pragma unroll
        for (int i = 0; i < 4; i++) { og[nt][i] = 0.f; ol[nt][i] = 0.f; }

    cp_wait1();            // Q + K(0) ready
    __syncthreads();

    for (int kt = 0; kt <= qb; kt++) {
        // ================= S = Q K^T (bf16x3) =================
        float s[8][4];
        #pragma unroll
        for (int nt = 0; nt < 8; nt++)
            #pragma unroll
            for (int i = 0; i < 4; i++) s[nt][i] = 0.f;

        #pragma unroll
        for (int kk = 0; kk < 8; kk++) {
            uint32_t ah[4], al[4];
            ldsm_x4(ah, aQh + kk * 32);
            ldsm_x4(al, aQl + kk * 32);
            uint32_t bh[8][2], bl[8][2];
            #pragma unroll
            for (int pr = 0; pr < 4; pr++) {
                const int r = pr * 16 + bKrow;
                uint32_t t4[4];
                ldsm_x4(t4, smem_u32(sKh + r * ASTR + kk * 16 + bKco));
                bh[2*pr][0]=t4[0]; bh[2*pr][1]=t4[1]; bh[2*pr+1][0]=t4[2]; bh[2*pr+1][1]=t4[3];
                ldsm_x4(t4, smem_u32(sKl + r * ASTR + kk * 16 + bKco));
                bl[2*pr][0]=t4[0]; bl[2*pr][1]=t4[1]; bl[2*pr+1][0]=t4[2]; bl[2*pr+1][1]=t4[3];
            }
            #pragma unroll
            for (int nt = 0; nt < 8; nt++) {
                mma16816(s[nt], ah, bh[nt]);
                mma16816(s[nt], ah, bl[nt]);
                mma16816(s[nt], al, bh[nt]);
            }
        }

        __syncthreads();                 // all warps done reading sK
        if (kt < qb) {                   // prefetch K(kt+1)
            const size_t gk = (size_t)((kt + 1) * BC + row) * HID + h * HD + half;
            #pragma unroll
            for (int i = 0; i < 8; i++) {
                cpa16(dKh + i * 16, Kh + gk + i * 8);
                cpa16(dKl + i * 16, Kl + gk + i * 8);
            }
        }
        cp_commit();
        cp_wait1();                      // V(kt) complete
        __syncthreads();

        // ================= masks + dual online softmax =================
        const bool diag = (kt == qb);
        const bool loct = (kt >= qb - 2);

        int kp[16];
        if (diag || loct) {
            #pragma unroll
            for (int nt = 0; nt < 8; nt++) {
                kp[2*nt]   = positions[kt * BC + 8 * nt + 2 * tg];
                kp[2*nt+1] = positions[kt * BC + 8 * nt + 2 * tg + 1];
            }
        }
        if (diag) {
            #pragma unroll
            for (int nt = 0; nt < 8; nt++)
                #pragma unroll
                for (int j = 0; j < 2; j++) {
                    if (qp0 < kp[2*nt+j]) s[nt][j]     = -1e30f;
                    if (qp1 < kp[2*nt+j]) s[nt][2 + j] = -1e30f;
                }
        }

        float mx0 = -1e30f, mx1 = -1e30f;
        #pragma unroll
        for (int nt = 0; nt < 8; nt++) {
            mx0 = fmaxf(mx0, fmaxf(s[nt][0], s[nt][1]));
            mx1 = fmaxf(mx1, fmaxf(s[nt][2], s[nt][3]));
        }
        mx0 = fmaxf(mx0, __shfl_xor_sync(0xffffffffu, mx0, 1));
        mx0 = fmaxf(mx0, __shfl_xor_sync(0xffffffffu, mx0, 2));
        mx1 = fmaxf(mx1, __shfl_xor_sync(0xffffffffu, mx1, 1));
        mx1 = fmaxf(mx1, __shfl_xor_sync(0xffffffffu, mx1, 2));

        const float mng0 = fmaxf(fmaxf(mg0, mx0), -1e28f);
        const float mng1 = fmaxf(fmaxf(mg1, mx1), -1e28f);
        const float alg0 = ex2(mg0 - mng0);
        const float alg1 = ex2(mg1 - mng1);

        uint32_t lmask = 0;
        float mnl0 = 0.f, mnl1 = 0.f, all0 = 0.f, all1 = 0.f;
        if (loct) {
            float mxl0 = -1e30f, mxl1 = -1e30f;
            #pragma unroll
            for (int nt = 0; nt < 8; nt++)
                #pragma unroll
                for (int j = 0; j < 2; j++) {
                    const int kpv = kp[2*nt+j];
                    if (qp0 >= kpv && qp0 - kpv < WIN) {
                        mxl0 = fmaxf(mxl0, s[nt][j]);
                        lmask |= 1u << (nt * 4 + j);
                    }
                    if (qp1 >= kpv && qp1 - kpv < WIN) {
                        mxl1 = fmaxf(mxl1, s[nt][2 + j]);
                        lmask |= 1u << (nt * 4 + 2 + j);
                    }
                }
            mxl0 = fmaxf(mxl0, __shfl_xor_sync(0xffffffffu, mxl0, 1));
            mxl0 = fmaxf(mxl0, __shfl_xor_sync(0xffffffffu, mxl0, 2));
            mxl1 = fmaxf(mxl1, __shfl_xor_sync(0xffffffffu, mxl1, 1));
            mxl1 = fmaxf(mxl1, __shfl_xor_sync(0xffffffffu, mxl1, 2));
            mnl0 = fmaxf(fmaxf(ml0, mxl0), -1e28f);
            mnl1 = fmaxf(fmaxf(ml1, mxl1), -1e28f);
            all0 = ex2(ml0 - mnl0);
            all1 = ex2(ml1 - mnl1);
        }

        float pl[8][4];
        float sg0 = 0.f, sg1 = 0.f, sl0 = 0.f, sl1 = 0.f;
        #pragma unroll
        for (int nt = 0; nt < 8; nt++) {
            #pragma unroll
            for (int j = 0; j < 2; j++) {
                float v0 = s[nt][j], v1 = s[nt][2 + j];
                float p0 = ex2(v0 - mng0); s[nt][j]     = p0; sg0 += p0;
                float p1 = ex2(v1 - mng1); s[nt][2 + j] = p1; sg1 += p1;
                if (loct) {
                    float q0 = (lmask >> (nt * 4 + j)) & 1u ? ex2(v0 - mnl0) : 0.f;
                    float q1 = (lmask >> (nt * 4 + 2 + j)) & 1u ? ex2(v1 - mnl1) : 0.f;
                    pl[nt][j] = q0;     sl0 += q0;
                    pl[nt][2 + j] = q1; sl1 += q1;
                }
            }
        }
        sg0 += __shfl_xor_sync(0xffffffffu, sg0, 1);
        sg0 += __shfl_xor_sync(0xffffffffu, sg0, 2);
        sg1 += __shfl_xor_sync(0xffffffffu, sg1, 1);
        sg1 += __shfl_xor_sync(0xffffffffu, sg1, 2);
        lg0 = lg0 * alg0 + sg0; mg0 = mng0;
        lg1 = lg1 * alg1 + sg1; mg1 = mng1;
        #pragma unroll
        for (int nt = 0; nt < 16; nt++) {
            og[nt][0] *= alg0; og[nt][1] *= alg0;
            og[nt][2] *= alg1; og[nt][3] *= alg1;
        }
        if (loct) {
            sl0 += __shfl_xor_sync(0xffffffffu, sl0, 1);
            sl0 += __shfl_xor_sync(0xffffffffu, sl0, 2);
            sl1 += __shfl_xor_sync(0xffffffffu, sl1, 1);
            sl1 += __shfl_xor_sync(0xffffffffu, sl1, 2);
            ll0 = ll0 * all0 + sl0; ml0 = mnl0;
            ll1 = ll1 * all1 + sl1; ml1 = mnl1;
            #pragma unroll
            for (int nt = 0; nt < 16; nt++) {
                ol[nt][0] *= all0; ol[nt][1] *= all0;
                ol[nt][2] *= all1; ol[nt][3] *= all1;
            }
        }

        // ================= O += P V (single-pass fp16) =================
        #pragma unroll
        for (int kk = 0; kk < 4; kk++) {
            uint32_t pg4[4], pl4[4];
            pg4[0] = packh2(s[2*kk][0],   s[2*kk][1]);
            pg4[1] = packh2(s[2*kk][2],   s[2*kk][3]);
            pg4[2] = packh2(s[2*kk+1][0], s[2*kk+1][1]);
            pg4[3] = packh2(s[2*kk+1][2], s[2*kk+1][3]);
            if (loct) {
                pl4[0] = packh2(pl[2*kk][0],   pl[2*kk][1]);
                pl4[1] = packh2(pl[2*kk][2],   pl[2*kk][3]);
                pl4[2] = packh2(pl[2*kk+1][0], pl[2*kk+1][1]);
                pl4[3] = packh2(pl[2*kk+1][2], pl[2*kk+1][3]);
            }
            #pragma unroll
            for (int dn = 0; dn < 8; dn++) {
                uint32_t v4[4];
                ldsm_x4_t(v4, smem_u32(sVf + (kk * 16 + vKrow) * ASTR + dn * 16 + vDco));
                mma16816h(og[2*dn],     pg4, &v4[0]);
                mma16816h(og[2*dn + 1], pg4, &v4[2]);
                if (loct) {
                    mma16816h(ol[2*dn],     pl4, &v4[0]);
                    mma16816h(ol[2*dn + 1], pl4, &v4[2]);
                }
            }
        }

        __syncthreads();                 // all warps done reading sV
        if (kt < qb) {                   // prefetch V(kt+1)
            const size_t gk = (size_t)((kt + 1) * BC + row) * HID + h * HD + half;
            #pragma unroll
            for (int i = 0; i < 8; i++)
                cpa16(dVf + i * 16, Vf + gk + i * 8);
        }
        cp_commit();
        cp_wait1();                      // K(kt+1) complete
        __syncthreads();
    }

    // ================= epilogue: gate selects accumulator =================
    const int t0 = qb * BR + warp * 16 + g;
    const bool u0 = qg[(size_t)t0 * NQG + NH * HD + h] > 0.f;
    const bool u1 = qg[(size_t)(t0 + 8) * NQG + NH * HD + h] > 0.f;
    const float inv0 = 1.f / (u0 ? lg0 : ll0);
    const float inv1 = 1.f / (u1 ? lg1 : ll1);
    #pragma unroll
    for (int nt = 0; nt < 16; nt++) {
        const int d = 8 * nt + 2 * tg;
        float a0 = (u0 ? og[nt][0] : ol[nt][0]) * inv0;
        float b0 = (u0 ? og[nt][1] : ol[nt][1]) * inv0;
        float a1 = (u1 ? og[nt][2] : ol[nt][2]) * inv1;
        float b1 = (u1 ? og[nt][3] : ol[nt][3]) * inv1;
        *(float2*)&outp[(size_t)t0 * HID + h * HD + d]       = make_float2(a0, b0);
        *(float2*)&outp[(size_t)(t0 + 8) * HID + h * HD + d] = make_float2(a1, b1);
    }
}

// ---------------------------------------------------------------------------
extern "C" void kernel_launch(void* const* d_in, const int* in_sizes, int n_in,
                              void* d_out, int out_size)
{
    const float* X   = (const float*)d_in[0];
    const int*   pos = (const int*)  d_in[1];
    const float* Wq  = (const float*)d_in[2];
    const float* Wk  = (const float*)d_in[3];
    const float* Wv  = (const float*)d_in[4];
    const float* Wo  = (const float*)d_in[5];
    const float* qw  = (const float*)d_in[6];
    const float* kw  = (const float*)d_in[7];
    float* out = (float*)d_out;

    float *qg, *kb, *vb, *bl;
    __nv_bfloat16 *Qh, *Ql, *Kh, *Kl;
    __half *Vf;
    cudaGetSymbolAddress((void**)&qg, d_qg);
    cudaGetSymbolAddress((void**)&kb, d_kbuf);
    cudaGetSymbolAddress((void**)&vb, d_vbuf);
    cudaGetSymbolAddress((void**)&bl, d_blend);
    cudaGetSymbolAddress((void**)&Qh, d_Qh);
    cudaGetSymbolAddress((void**)&Ql, d_Ql);
    cudaGetSymbolAddress((void**)&Kh, d_Kh);
    cudaGetSymbolAddress((void**)&Kl, d_Kl);
    cudaGetSymbolAddress((void**)&Vf, d_Vf);

    cudaFuncSetAttribute(mma_gemm, cudaFuncAttributeMaxDynamicSharedMemorySize,
                         GEMM_SMEM);
    cudaFuncSetAttribute(attn_mma_kernel, cudaFuncAttributeMaxDynamicSharedMemorySize,
                         ATTN_SMEM);

    dim3 blk(256);
    dim3 gtile(16, 16);

    mma_gemm<<<gtile, blk, GEMM_SMEM>>>(X, Wq, qg, HID, NQG, NQG);
    sgemm_kernel<<<dim3(1, 16), blk>>>(X, Wq + NH * HD, qg + NH * HD,
                                       T_TOK, NH, HID, NQG, NQG);
    mma_gemm<<<gtile, blk, GEMM_SMEM>>>(X, Wk, kb, HID, HID, HID);
    mma_gemm<<<gtile, blk, GEMM_SMEM>>>(X, Wv, vb, HID, HID, HID);

    norm_rope_kernel<<<T_TOK, 256>>>(qg, kb, vb, qw, kw, pos,
                                     Qh, Ql, Kh, Kl, Vf);

    dim3 ga(T_TOK / BR, NH);   // 32 x 16
    attn_mma_kernel<<<ga, 128, ATTN_SMEM>>>(Qh, Ql, Kh, Kl, Vf,
                                            qg, bl, pos);

    mma_gemm<<<gtile, blk, GEMM_SMEM>>>(bl, Wo, out, HID, HID, HID);
}

// round 16
// speedup vs baseline: 2.3275x; 1.0228x over previous
#include <cuda_runtime.h>
#include <cuda_bf16.h>
#include <cuda_fp16.h>
#include <math.h>
#include <stdint.h>

#define T_TOK 2048
#define HID   2048
#define NH    16
#define HD    128
#define NQG   2064      // H*D + H
#define WIN   128

// ---------------- scratch (static device globals; no runtime allocation) ----
__device__ float d_qg[T_TOK * NQG];     // X @ Wq  (gate cols 2048..2063)
__device__ float d_kbuf[T_TOK * HID];   // X @ Wk (pre-norm)
__device__ float d_vbuf[T_TOK * HID];   // X @ Wv

__device__ __nv_bfloat16 d_Xh[T_TOK * HID];   // X split
__device__ __nv_bfloat16 d_Xl[T_TOK * HID];
__device__ __nv_bfloat16 d_WqTh[HID * HID];   // transposed weight splits [n][k]
__device__ __nv_bfloat16 d_WqTl[HID * HID];
__device__ __nv_bfloat16 d_WkTh[HID * HID];
__device__ __nv_bfloat16 d_WkTl[HID * HID];
__device__ __nv_bfloat16 d_WvTh[HID * HID];
__device__ __nv_bfloat16 d_WvTl[HID * HID];
__device__ __nv_bfloat16 d_WoTh[HID * HID];
__device__ __nv_bfloat16 d_WoTl[HID * HID];
__device__ __nv_bfloat16 d_Bh[T_TOK * HID];   // blended attention out (hi/lo)
__device__ __nv_bfloat16 d_Bl[T_TOK * HID];

__device__ __nv_bfloat16 d_Qh[T_TOK * HID];
__device__ __nv_bfloat16 d_Ql[T_TOK * HID];
__device__ __nv_bfloat16 d_Kh[T_TOK * HID];
__device__ __nv_bfloat16 d_Kl[T_TOK * HID];
__device__ __half        d_Vf[T_TOK * HID];

// ---------------- common helpers -------------------------------------------
__device__ __forceinline__ uint32_t smem_u32(const void* p) {
    return (uint32_t)__cvta_generic_to_shared(p);
}
__device__ __forceinline__ void ldsm_x4(uint32_t* r, uint32_t addr) {
    asm volatile("ldmatrix.sync.aligned.m8n8.x4.shared.b16 {%0,%1,%2,%3}, [%4];\n"
        : "=r"(r[0]), "=r"(r[1]), "=r"(r[2]), "=r"(r[3]) : "r"(addr));
}
__device__ __forceinline__ void ldsm_x4_t(uint32_t* r, uint32_t addr) {
    asm volatile("ldmatrix.sync.aligned.m8n8.x4.trans.shared.b16 {%0,%1,%2,%3}, [%4];\n"
        : "=r"(r[0]), "=r"(r[1]), "=r"(r[2]), "=r"(r[3]) : "r"(addr));
}
__device__ __forceinline__ void mma16816(float* d, const uint32_t* a, const uint32_t* b) {
    asm volatile(
        "mma.sync.aligned.m16n8k16.row.col.f32.bf16.bf16.f32 "
        "{%0,%1,%2,%3}, {%4,%5,%6,%7}, {%8,%9}, {%0,%1,%2,%3};\n"
        : "+f"(d[0]), "+f"(d[1]), "+f"(d[2]), "+f"(d[3])
        : "r"(a[0]), "r"(a[1]), "r"(a[2]), "r"(a[3]), "r"(b[0]), "r"(b[1]));
}
__device__ __forceinline__ void mma16816h(float* d, const uint32_t* a, const uint32_t* b) {
    asm volatile(
        "mma.sync.aligned.m16n8k16.row.col.f32.f16.f16.f32 "
        "{%0,%1,%2,%3}, {%4,%5,%6,%7}, {%8,%9}, {%0,%1,%2,%3};\n"
        : "+f"(d[0]), "+f"(d[1]), "+f"(d[2]), "+f"(d[3])
        : "r"(a[0]), "r"(a[1]), "r"(a[2]), "r"(a[3]), "r"(b[0]), "r"(b[1]));
}
__device__ __forceinline__ uint32_t packh2(float a, float b) {
    __half2 h = __floats2half2_rn(a, b);
    return *(uint32_t*)&h;
}
__device__ __forceinline__ float ex2(float x) {
    float y;
    asm("ex2.approx.ftz.f32 %0, %1;" : "=f"(y) : "f"(x));
    return y;
}
__device__ __forceinline__ void split2(float a, float b, uint32_t& hi, uint32_t& lo) {
    __nv_bfloat16 ha = __float2bfloat16(a), hb = __float2bfloat16(b);
    __nv_bfloat162 H, L;
    H.x = ha; H.y = hb;
    L.x = __float2bfloat16(a - __bfloat162float(ha));
    L.y = __float2bfloat16(b - __bfloat162float(hb));
    hi = *(uint32_t*)&H; lo = *(uint32_t*)&L;
}
__device__ __forceinline__ void cpa16(uint32_t dst, const void* src) {
    asm volatile("cp.async.cg.shared.global [%0], [%1], 16;\n" :: "r"(dst), "l"(src));
}
__device__ __forceinline__ void cp_commit() {
    asm volatile("cp.async.commit_group;\n" ::: "memory");
}
__device__ __forceinline__ void cp_wait0() {
    asm volatile("cp.async.wait_group 0;\n" ::: "memory");
}
__device__ __forceinline__ void cp_wait1() {
    asm volatile("cp.async.wait_group 1;\n" ::: "memory");
}

// ============================================================================
// operand prep kernels
// ============================================================================

// X [M,K] fp32 -> hi/lo bf16 (row-major, same layout)
__global__ __launch_bounds__(256) void split_x(
    const float* __restrict__ X,
    __nv_bfloat16* __restrict__ Xh, __nv_bfloat16* __restrict__ Xl)
{
    const size_t base = ((size_t)blockIdx.x * 256 + threadIdx.x) * 8;
    float v[8];
    *(float4*)v       = *(const float4*)(X + base);
    *(float4*)(v + 4) = *(const float4*)(X + base + 4);
    union { __nv_bfloat16 b[8]; uint4 u; } ph, pl;
    #pragma unroll
    for (int j = 0; j < 8; j++) {
        __nv_bfloat16 h = __float2bfloat16(v[j]);
        ph.b[j] = h;
        pl.b[j] = __float2bfloat16(v[j] - __bfloat162float(h));
    }
    *(uint4*)(Xh + base) = ph.u;
    *(uint4*)(Xl + base) = pl.u;
}

// W [K=2048 rows, ld cols] fp32 -> transposed hi/lo bf16 [n][k] (2048x2048)
__global__ __launch_bounds__(256) void splitT(
    const float* __restrict__ W, int ld,
    __nv_bfloat16* __restrict__ Th, __nv_bfloat16* __restrict__ Tl)
{
    __shared__ float tile[32][36];
    const int k0 = blockIdx.y * 32, n0 = blockIdx.x * 32;
    const int tid = threadIdx.x;

    // load 32x32 fp32 tile (rows = k), float4 per thread
    {
        const int i = tid >> 3, c4 = (tid & 7) * 4;
        *(float4*)&tile[i][c4] = *(const float4*)(W + (size_t)(k0 + i) * ld + n0 + c4);
    }
    __syncthreads();

    // write transposed hi/lo, 2 bf16 packed per store
    const int tx = tid & 15;          // k-pair index
    const int ty = tid >> 4;          // n (first half)
    #pragma unroll
    for (int rep = 0; rep < 2; rep++) {
        const int n = ty + rep * 16;
        float a = tile[2 * tx][n];
        float b = tile[2 * tx + 1][n];
        uint32_t hi, lo;
        split2(a, b, hi, lo);
        const size_t o = (size_t)(n0 + n) * HID + k0 + 2 * tx;
        *(uint32_t*)(Th + o) = hi;
        *(uint32_t*)(Tl + o) = lo;
    }
}

// exact fp32 thin GEMM for the 16 gate columns: qg[:,2048+c] = X @ Wq[:,2048+c]
__global__ __launch_bounds__(256) void gate_gemm(
    const float* __restrict__ X, const float* __restrict__ Wq,
    float* __restrict__ qg)
{
    const int c   = threadIdx.x & 15;
    const int r   = threadIdx.x >> 4;
    const int row = blockIdx.x * 16 + r;
    const float* x = X + (size_t)row * HID;
    const float* w = Wq + NH * HD + c;

    float acc = 0.f;
    #pragma unroll 8
    for (int k = 0; k < HID; k += 4) {
        float4 xv = *(const float4*)(x + k);
        acc = fmaf(xv.x, w[(size_t)k * NQG],       acc);
        acc = fmaf(xv.y, w[(size_t)(k + 1) * NQG], acc);
        acc = fmaf(xv.z, w[(size_t)(k + 2) * NQG], acc);
        acc = fmaf(xv.w, w[(size_t)(k + 3) * NQG], acc);
    }
    qg[(size_t)row * NQG + NH * HD + c] = acc;
}

// ============================================================================
// bf16x3 tensor-core GEMM on PRE-SPLIT operands.
// A: row-major [M,K] hi/lo bf16.  B: transposed [N,K] hi/lo bf16.
// C fp32 [M,N] (ldc).  128x128 tile, BK=16, cp.async double buffer.
// ============================================================================
#define SSTR 24
#define GSTAGE_B (4 * 128 * SSTR * 2)      // stage bytes = 24576
#define ALO_B (128 * SSTR * 2)
#define BHI_B (2 * 128 * SSTR * 2)
#define BLO_B (3 * 128 * SSTR * 2)
#define GEMM_SMEM (2 * GSTAGE_B)           // 49152

__global__ __launch_bounds__(256, 2) void mma_gemm_b(
    const __nv_bfloat16* __restrict__ Ahg, const __nv_bfloat16* __restrict__ Alg,
    const __nv_bfloat16* __restrict__ Bhg, const __nv_bfloat16* __restrict__ Blg,
    float* __restrict__ C, int K, int ldc)
{
    extern __shared__ char smraw[];
    __nv_bfloat16* sm = (__nv_bfloat16*)smraw;

    const int tid  = threadIdx.x;
    const int warp = tid >> 5, lane = tid & 31;
    const int bm   = blockIdx.y * 128, bn = blockIdx.x * 128;

    const int row = tid >> 1;             // 0..127 (both A row and B n-row)
    const int ch  = (tid & 1) * 8;        // k chunk (8 bf16 = 16B)

    const int wm = (warp & 3) * 32;
    const int wn = (warp >> 2) * 64;
    const int g  = lane >> 2, tg = lane & 3;

    const uint32_t dst0 = smem_u32(sm) + row * 48 + ch * 2;

    float acc[2][8][4];
    #pragma unroll
    for (int mt = 0; mt < 2; mt++)
        #pragma unroll
        for (int nt = 0; nt < 8; nt++)
            #pragma unroll
            for (int i = 0; i < 4; i++) acc[mt][nt][i] = 0.f;

    // prologue: stage 0
    {
        const size_t ao = (size_t)(bm + row) * K + ch;
        const size_t bo = (size_t)(bn + row) * K + ch;
        cpa16(dst0,         Ahg + ao);
        cpa16(dst0 + ALO_B, Alg + ao);
        cpa16(dst0 + BHI_B, Bhg + bo);
        cpa16(dst0 + BLO_B, Blg + bo);
        cp_commit();
    }

    const int KT = K >> 4;   // 128
    for (int kt = 0; kt < KT; kt++) {
        const uint32_t cur = (kt & 1) ? GSTAGE_B : 0;

        if (kt + 1 < KT) {
            const int k0 = (kt + 1) << 4;
            const uint32_t nd = dst0 + ((kt + 1) & 1) * GSTAGE_B;
            const size_t ao = (size_t)(bm + row) * K + k0 + ch;
            const size_t bo = (size_t)(bn + row) * K + k0 + ch;
            cpa16(nd,         Ahg + ao);
            cpa16(nd + ALO_B, Alg + ao);
            cpa16(nd + BHI_B, Bhg + bo);
            cpa16(nd + BLO_B, Blg + bo);
            cp_commit();
            cp_wait1();
        } else {
            cp_wait0();
        }
        __syncthreads();

        const __nv_bfloat16* Ah = (const __nv_bfloat16*)(smraw + cur);
        const __nv_bfloat16* Al = (const __nv_bfloat16*)(smraw + cur + ALO_B);
        const __nv_bfloat16* Bh = (const __nv_bfloat16*)(smraw + cur + BHI_B);
        const __nv_bfloat16* Bl = (const __nv_bfloat16*)(smraw + cur + BLO_B);

        uint32_t ah[2][4], al[2][4];
        #pragma unroll
        for (int mt = 0; mt < 2; mt++) {
            const int r = wm + mt * 16 + (lane & 15);
            const int co = (lane >> 4) * 8;
            ldsm_x4(ah[mt], smem_u32(Ah + r * SSTR + co));
            ldsm_x4(al[mt], smem_u32(Al + r * SSTR + co));
        }
        uint32_t bh[8][2], bl[8][2];
        #pragma unroll
        for (int pr = 0; pr < 4; pr++) {
            const int r  = wn + pr * 16 + (lane & 7) + ((lane & 16) >> 1);
            const int co = lane & 8;
            uint32_t t[4];
            ldsm_x4(t, smem_u32(Bh + r * SSTR + co));
            bh[2*pr][0]=t[0]; bh[2*pr][1]=t[1]; bh[2*pr+1][0]=t[2]; bh[2*pr+1][1]=t[3];
            ldsm_x4(t, smem_u32(Bl + r * SSTR + co));
            bl[2*pr][0]=t[0]; bl[2*pr][1]=t[1]; bl[2*pr+1][0]=t[2]; bl[2*pr+1][1]=t[3];
        }

        #pragma unroll
        for (int mt = 0; mt < 2; mt++)
            #pragma unroll
            for (int nt = 0; nt < 8; nt++) {
                mma16816(acc[mt][nt], ah[mt], bh[nt]);
                mma16816(acc[mt][nt], ah[mt], bl[nt]);
                mma16816(acc[mt][nt], al[mt], bh[nt]);
            }
        __syncthreads();   // reads done before next iter's cp.async overwrite
    }

    #pragma unroll
    for (int mt = 0; mt < 2; mt++) {
        const int r0 = bm + wm + mt * 16 + g;
        #pragma unroll
        for (int nt = 0; nt < 8; nt++) {
            const int c = bn + wn + nt * 8 + tg * 2;
            *(float2*)&C[(size_t)r0 * ldc + c] =
                make_float2(acc[mt][nt][0], acc[mt][nt][1]);
            *(float2*)&C[(size_t)(r0 + 8) * ldc + c] =
                make_float2(acc[mt][nt][2], acc[mt][nt][3]);
        }
    }
}

// ---------------- RMSNorm + RoPE + bf16 hi/lo split (q,k), fp16 v ----------
__global__ __launch_bounds__(256) void norm_rope_kernel(
    const float* __restrict__ qg, const float* __restrict__ kb,
    const float* __restrict__ vb,
    const float* __restrict__ qw, const float* __restrict__ kw,
    const int* __restrict__ positions,
    __nv_bfloat16* __restrict__ Qh, __nv_bfloat16* __restrict__ Ql,
    __nv_bfloat16* __restrict__ Kh, __nv_bfloat16* __restrict__ Kl,
    __half* __restrict__ Vf)
{
    const int t   = blockIdx.x;
    const int tid = threadIdx.x;
    __shared__ float red[256];
    __shared__ float cs[64], sn[64];
    __shared__ float rq_s, rk_s;

    const float* qrow = qg + (size_t)t * NQG;
    const float* krow = kb + (size_t)t * HID;
    const float* vrow = vb + (size_t)t * HID;
    const float scale = 0.08838834764831843f * 1.4426950408889634f;

    float sq = 0.f, sk = 0.f;
    for (int i = tid; i < HID; i += 256) {
        float a = qrow[i]; sq = fmaf(a, a, sq);
        float b = krow[i]; sk = fmaf(b, b, sk);
    }
    red[tid] = sq; __syncthreads();
    for (int s = 128; s > 0; s >>= 1) { if (tid < s) red[tid] += red[tid + s]; __syncthreads(); }
    if (tid == 0) rq_s = rsqrtf(red[0] * (1.f / (float)HID) + 1e-6f);
    __syncthreads();
    red[tid] = sk; __syncthreads();
    for (int s = 128; s > 0; s >>= 1) { if (tid < s) red[tid] += red[tid + s]; __syncthreads(); }
    if (tid == 0) rk_s = rsqrtf(red[0] * (1.f / (float)HID) + 1e-6f);

    if (tid < 64) {
        double invf = exp(-(double)tid * (log(500000.0) / 64.0));
        double ang  = (double)positions[t] * invf;
        double sd, cd;
        sincos(ang, &sd, &cd);
        cs[tid] = (float)cd;
        sn[tid] = (float)sd;
    }
    __syncthreads();

    const float rq = rq_s, rk = rk_s;
    for (int pid = tid; pid < NH * 64; pid += 256) {
        int hh = pid >> 6, j = pid & 63;
        int i1 = hh * HD + j, i2 = i1 + 64;
        float c = cs[j], s = sn[j];
        float x1 = qrow[i1] * rq * qw[i1];
        float x2 = qrow[i2] * rq * qw[i2];
        float q1 = (x1 * c - x2 * s) * scale;
        float q2 = (x2 * c + x1 * s) * scale;
        float y1 = krow[i1] * rk * kw[i1];
        float y2 = krow[i2] * rk * kw[i2];
        float k1 = y1 * c - y2 * s;
        float k2 = y2 * c + y1 * s;

        size_t b = (size_t)t * HID;
        __nv_bfloat16 h;
        h = __float2bfloat16(q1); Qh[b+i1] = h; Ql[b+i1] = __float2bfloat16(q1 - __bfloat162float(h));
        h = __float2bfloat16(q2); Qh[b+i2] = h; Ql[b+i2] = __float2bfloat16(q2 - __bfloat162float(h));
        h = __float2bfloat16(k1); Kh[b+i1] = h; Kl[b+i1] = __float2bfloat16(k1 - __bfloat162float(h));
        h = __float2bfloat16(k2); Kh[b+i2] = h; Kl[b+i2] = __float2bfloat16(k2 - __bfloat162float(h));
    }
    for (int i = tid; i < HID; i += 256) {
        size_t b = (size_t)t * HID + i;
        Vf[b] = __float2half_rn(vrow[i]);
    }
}

// ============================================================================
// Fused-pass tensor-core dual attention, cp.async K/V ping-pong.
// QK^T: bf16x3.  PV: single-pass fp16.  exp via ex2.
// Epilogue writes blended output as bf16 hi/lo (feeds Wo GEMM directly).
// ============================================================================
#define BR 64
#define BC 64
#define ASTR 136
#define ATTN_SMEM (5 * BC * ASTR * 2)

__global__ __launch_bounds__(128, 2) void attn_mma_kernel(
    const __nv_bfloat16* __restrict__ Qh, const __nv_bfloat16* __restrict__ Ql,
    const __nv_bfloat16* __restrict__ Kh, const __nv_bfloat16* __restrict__ Kl,
    const __half* __restrict__ Vf,
    const float* __restrict__ qg,
    __nv_bfloat16* __restrict__ Bh_o, __nv_bfloat16* __restrict__ Bl_o,
    const int* __restrict__ positions)
{
    extern __shared__ char smraw[];
    __nv_bfloat16* sQh = (__nv_bfloat16*)smraw;
    __nv_bfloat16* sQl = sQh + BR * ASTR;
    __nv_bfloat16* sKh = sQl + BR * ASTR;
    __nv_bfloat16* sKl = sKh + BC * ASTR;
    __half*        sVf = (__half*)(sKl + BC * ASTR);

    const int qb   = (int)gridDim.x - 1 - (int)blockIdx.x;
    const int h    = blockIdx.y;
    const int tid  = threadIdx.x;
    const int warp = tid >> 5, lane = tid & 31;
    const int g = lane >> 2, tg = lane & 3;

    const int  row  = tid >> 1;
    const int  half = (tid & 1) * 64;
    const uint32_t dKh = smem_u32(sKh + row * ASTR + half);
    const uint32_t dKl = smem_u32(sKl + row * ASTR + half);
    const uint32_t dVf = smem_u32(sVf + row * ASTR + half);

    {
        const size_t gq = (size_t)(qb * BR + row) * HID + h * HD + half;
        const uint32_t dQh = smem_u32(sQh + row * ASTR + half);
        const uint32_t dQl = smem_u32(sQl + row * ASTR + half);
        #pragma unroll
        for (int i = 0; i < 8; i++) {
            cpa16(dQh + i * 16, Qh + gq + i * 8);
            cpa16(dQl + i * 16, Ql + gq + i * 8);
        }
        const size_t gk = (size_t)row * HID + h * HD + half;
        #pragma unroll
        for (int i = 0; i < 8; i++) {
            cpa16(dKh + i * 16, Kh + gk + i * 8);
            cpa16(dKl + i * 16, Kl + gk + i * 8);
        }
        cp_commit();
        #pragma unroll
        for (int i = 0; i < 8; i++)
            cpa16(dVf + i * 16, Vf + gk + i * 8);
        cp_commit();
    }

    const int qp0 = positions[qb * BR + warp * 16 + g];
    const int qp1 = positions[qb * BR + warp * 16 + g + 8];

    const uint32_t aQh = smem_u32(sQh + (warp * 16 + (lane & 15)) * ASTR + (lane >> 4) * 8);
    const uint32_t aQl = smem_u32(sQl + (warp * 16 + (lane & 15)) * ASTR + (lane >> 4) * 8);
    const int bKrow = (lane & 7) + ((lane & 16) >> 1);
    const int bKco  = lane & 8;
    const int vKrow = (lane & 8) + (lane & 7);
    const int vDco  = (lane & 16) >> 1;

    float mg0 = -1e30f, mg1 = -1e30f, lg0 = 0.f, lg1 = 0.f;
    float ml0 = -1e30f, ml1 = -1e30f, ll0 = 0.f, ll1 = 0.f;
    float og[16][4], ol[16][4];
    #pragma unroll
    for (int nt = 0; nt < 16; nt++)
        #pragma unroll
        for (int i = 0; i < 4; i++) { og[nt][i] = 0.f; ol[nt][i] = 0.f; }

    cp_wait1();
    __syncthreads();

    for (int kt = 0; kt <= qb; kt++) {
        float s[8][4];
        #pragma unroll
        for (int nt = 0; nt < 8; nt++)
            #pragma unroll
            for (int i = 0; i < 4; i++) s[nt][i] = 0.f;

        #pragma unroll
        for (int kk = 0; kk < 8; kk++) {
            uint32_t ah[4], al[4];
            ldsm_x4(ah, aQh + kk * 32);
            ldsm_x4(al, aQl + kk * 32);
            uint32_t bh[8][2], bl[8][2];
            #pragma unroll
            for (int pr = 0; pr < 4; pr++) {
                const int r = pr * 16 + bKrow;
                uint32_t t4[4];
                ldsm_x4(t4, smem_u32(sKh + r * ASTR + kk * 16 + bKco));
                bh[2*pr][0]=t4[0]; bh[2*pr][1]=t4[1]; bh[2*pr+1][0]=t4[2]; bh[2*pr+1][1]=t4[3];
                ldsm_x4(t4, smem_u32(sKl + r * ASTR + kk * 16 + bKco));
                bl[2*pr][0]=t4[0]; bl[2*pr][1]=t4[1]; bl[2*pr+1][0]=t4[2]; bl[2*pr+1][1]=t4[3];
            }
            #pragma unroll
            for (int nt = 0; nt < 8; nt++) {
                mma16816(s[nt], ah, bh[nt]);
                mma16816(s[nt], ah, bl[nt]);
                mma16816(s[nt], al, bh[nt]);
            }
        }

        __syncthreads();
        if (kt < qb) {
            const size_t gk = (size_t)((kt + 1) * BC + row) * HID + h * HD + half;
            #pragma unroll
            for (int i = 0; i < 8; i++) {
                cpa16(dKh + i * 16, Kh + gk + i * 8);
                cpa16(dKl + i * 16, Kl + gk + i * 8);
            }
        }
        cp_commit();
        cp_wait1();
        __syncthreads();

        const bool diag = (kt == qb);
        const bool loct = (kt >= qb - 2);

        int kp[16];
        if (diag || loct) {
            #pragma unroll
            for (int nt = 0; nt < 8; nt++) {
                kp[2*nt]   = positions[kt * BC + 8 * nt + 2 * tg];
                kp[2*nt+1] = positions[kt * BC + 8 * nt + 2 * tg + 1];
            }
        }
        if (diag) {
            #pragma unroll
            for (int nt = 0; nt < 8; nt++)
                #pragma unroll
                for (int j = 0; j < 2; j++) {
                    if (qp0 < kp[2*nt+j]) s[nt][j]     = -1e30f;
                    if (qp1 < kp[2*nt+j]) s[nt][2 + j] = -1e30f;
                }
        }

        float mx0 = -1e30f, mx1 = -1e30f;
        #pragma unroll
        for (int nt = 0; nt < 8; nt++) {
            mx0 = fmaxf(mx0, fmaxf(s[nt][0], s[nt][1]));
            mx1 = fmaxf(mx1, fmaxf(s[nt][2], s[nt][3]));
        }
        mx0 = fmaxf(mx0, __shfl_xor_sync(0xffffffffu, mx0, 1));
        mx0 = fmaxf(mx0, __shfl_xor_sync(0xffffffffu, mx0, 2));
        mx1 = fmaxf(mx1, __shfl_xor_sync(0xffffffffu, mx1, 1));
        mx1 = fmaxf(mx1, __shfl_xor_sync(0xffffffffu, mx1, 2));

        const float mng0 = fmaxf(fmaxf(mg0, mx0), -1e28f);
        const float mng1 = fmaxf(fmaxf(mg1, mx1), -1e28f);
        const float alg0 = ex2(mg0 - mng0);
        const float alg1 = ex2(mg1 - mng1);

        uint32_t lmask = 0;
        float mnl0 = 0.f, mnl1 = 0.f, all0 = 0.f, all1 = 0.f;
        if (loct) {
            float mxl0 = -1e30f, mxl1 = -1e30f;
            #pragma unroll
            for (int nt = 0; nt < 8; nt++)
                #pragma unroll
                for (int j = 0; j < 2; j++) {
                    const int kpv = kp[2*nt+j];
                    if (qp0 >= kpv && qp0 - kpv < WIN) {
                        mxl0 = fmaxf(mxl0, s[nt][j]);
                        lmask |= 1u << (nt * 4 + j);
                    }
                    if (qp1 >= kpv && qp1 - kpv < WIN) {
                        mxl1 = fmaxf(mxl1, s[nt][2 + j]);
                        lmask |= 1u << (nt * 4 + 2 + j);
                    }
                }
            mxl0 = fmaxf(mxl0, __shfl_xor_sync(0xffffffffu, mxl0, 1));
            mxl0 = fmaxf(mxl0, __shfl_xor_sync(0xffffffffu, mxl0, 2));
            mxl1 = fmaxf(mxl1, __shfl_xor_sync(0xffffffffu, mxl1, 1));
            mxl1 = fmaxf(mxl1, __shfl_xor_sync(0xffffffffu, mxl1, 2));
            mnl0 = fmaxf(fmaxf(ml0, mxl0), -1e28f);
            mnl1 = fmaxf(fmaxf(ml1, mxl1), -1e28f);
            all0 = ex2(ml0 - mnl0);
            all1 = ex2(ml1 - mnl1);
        }

        float pl[8][4];
        float sg0 = 0.f, sg1 = 0.f, sl0 = 0.f, sl1 = 0.f;
        #pragma unroll
        for (int nt = 0; nt < 8; nt++) {
            #pragma unroll
            for (int j = 0; j < 2; j++) {
                float v0 = s[nt][j], v1 = s[nt][2 + j];
                float p0 = ex2(v0 - mng0); s[nt][j]     = p0; sg0 += p0;
                float p1 = ex2(v1 - mng1); s[nt][2 + j] = p1; sg1 += p1;
                if (loct) {
                    float q0 = (lmask >> (nt * 4 + j)) & 1u ? ex2(v0 - mnl0) : 0.f;
                    float q1 = (lmask >> (nt * 4 + 2 + j)) & 1u ? ex2(v1 - mnl1) : 0.f;
                    pl[nt][j] = q0;     sl0 += q0;
                    pl[nt][2 + j] = q1; sl1 += q1;
                }
            }
        }
        sg0 += __shfl_xor_sync(0xffffffffu, sg0, 1);
        sg0 += __shfl_xor_sync(0xffffffffu, sg0, 2);
        sg1 += __shfl_xor_sync(0xffffffffu, sg1, 1);
        sg1 += __shfl_xor_sync(0xffffffffu, sg1, 2);
        lg0 = lg0 * alg0 + sg0; mg0 = mng0;
        lg1 = lg1 * alg1 + sg1; mg1 = mng1;
        #pragma unroll
        for (int nt = 0; nt < 16; nt++) {
            og[nt][0] *= alg0; og[nt][1] *= alg0;
            og[nt][2] *= alg1; og[nt][3] *= alg1;
        }
        if (loct) {
            sl0 += __shfl_xor_sync(0xffffffffu, sl0, 1);
            sl0 += __shfl_xor_sync(0xffffffffu, sl0, 2);
            sl1 += __shfl_xor_sync(0xffffffffu, sl1, 1);
            sl1 += __shfl_xor_sync(0xffffffffu, sl1, 2);
            ll0 = ll0 * all0 + sl0; ml0 = mnl0;
            ll1 = ll1 * all1 + sl1; ml1 = mnl1;
            #pragma unroll
            for (int nt = 0; nt < 16; nt++) {
                ol[nt][0] *= all0; ol[nt][1] *= all0;
                ol[nt][2] *= all1; ol[nt][3] *= all1;
            }
        }

        #pragma unroll
        for (int kk = 0; kk < 4; kk++) {
            uint32_t pg4[4], pl4[4];
            pg4[0] = packh2(s[2*kk][0],   s[2*kk][1]);
            pg4[1] = packh2(s[2*kk][2],   s[2*kk][3]);
            pg4[2] = packh2(s[2*kk+1][0], s[2*kk+1][1]);
            pg4[3] = packh2(s[2*kk+1][2], s[2*kk+1][3]);
            if (loct) {
                pl4[0] = packh2(pl[2*kk][0],   pl[2*kk][1]);
                pl4[1] = packh2(pl[2*kk][2],   pl[2*kk][3]);
                pl4[2] = packh2(pl[2*kk+1][0], pl[2*kk+1][1]);
                pl4[3] = packh2(pl[2*kk+1][2], pl[2*kk+1][3]);
            }
            #pragma unroll
            for (int dn = 0; dn < 8; dn++) {
                uint32_t v4[4];
                ldsm_x4_t(v4, smem_u32(sVf + (kk * 16 + vKrow) * ASTR + dn * 16 + vDco));
                mma16816h(og[2*dn],     pg4, &v4[0]);
                mma16816h(og[2*dn + 1], pg4, &v4[2]);
                if (loct) {
                    mma16816h(ol[2*dn],     pl4, &v4[0]);
                    mma16816h(ol[2*dn + 1], pl4, &v4[2]);
                }
            }
        }

        __syncthreads();
        if (kt < qb) {
            const size_t gk = (size_t)((kt + 1) * BC + row) * HID + h * HD + half;
            #pragma unroll
            for (int i = 0; i < 8; i++)
                cpa16(dVf + i * 16, Vf + gk + i * 8);
        }
        cp_commit();
        cp_wait1();
        __syncthreads();
    }

    // ---- epilogue: gate select + normalize, emit bf16 hi/lo for Wo GEMM
    const int t0 = qb * BR + warp * 16 + g;
    const bool u0 = qg[(size_t)t0 * NQG + NH * HD + h] > 0.f;
    const bool u1 = qg[(size_t)(t0 + 8) * NQG + NH * HD + h] > 0.f;
    const float inv0 = 1.f / (u0 ? lg0 : ll0);
    const float inv1 = 1.f / (u1 ? lg1 : ll1);
    #pragma unroll
    for (int nt = 0; nt < 16; nt++) {
        const int d = 8 * nt + 2 * tg;
        float a0 = (u0 ? og[nt][0] : ol[nt][0]) * inv0;
        float b0 = (u0 ? og[nt][1] : ol[nt][1]) * inv0;
        float a1 = (u1 ? og[nt][2] : ol[nt][2]) * inv1;
        float b1 = (u1 ? og[nt][3] : ol[nt][3]) * inv1;
        uint32_t hi, lo;
        split2(a0, b0, hi, lo);
        *(uint32_t*)(Bh_o + (size_t)t0 * HID + h * HD + d) = hi;
        *(uint32_t*)(Bl_o + (size_t)t0 * HID + h * HD + d) = lo;
        split2(a1, b1, hi, lo);
        *(uint32_t*)(Bh_o + (size_t)(t0 + 8) * HID + h * HD + d) = hi;
        *(uint32_t*)(Bl_o + (size_t)(t0 + 8) * HID + h * HD + d) = lo;
    }
}

// ---------------------------------------------------------------------------
extern "C" void kernel_launch(void* const* d_in, const int* in_sizes, int n_in,
                              void* d_out, int out_size)
{
    const float* X   = (const float*)d_in[0];
    const int*   pos = (const int*)  d_in[1];
    const float* Wq  = (const float*)d_in[2];
    const float* Wk  = (const float*)d_in[3];
    const float* Wv  = (const float*)d_in[4];
    const float* Wo  = (const float*)d_in[5];
    const float* qw  = (const float*)d_in[6];
    const float* kw  = (const float*)d_in[7];
    float* out = (float*)d_out;

    float *qg, *kb, *vb;
    __nv_bfloat16 *Xh, *Xl, *WqTh, *WqTl, *WkTh, *WkTl, *WvTh, *WvTl,
                  *WoTh, *WoTl, *Bh, *Bl, *Qh, *Ql, *Kh, *Kl;
    __half *Vf;
    cudaGetSymbolAddress((void**)&qg, d_qg);
    cudaGetSymbolAddress((void**)&kb, d_kbuf);
    cudaGetSymbolAddress((void**)&vb, d_vbuf);
    cudaGetSymbolAddress((void**)&Xh, d_Xh);
    cudaGetSymbolAddress((void**)&Xl, d_Xl);
    cudaGetSymbolAddress((void**)&WqTh, d_WqTh);
    cudaGetSymbolAddress((void**)&WqTl, d_WqTl);
    cudaGetSymbolAddress((void**)&WkTh, d_WkTh);
    cudaGetSymbolAddress((void**)&WkTl, d_WkTl);
    cudaGetSymbolAddress((void**)&WvTh, d_WvTh);
    cudaGetSymbolAddress((void**)&WvTl, d_WvTl);
    cudaGetSymbolAddress((void**)&WoTh, d_WoTh);
    cudaGetSymbolAddress((void**)&WoTl, d_WoTl);
    cudaGetSymbolAddress((void**)&Bh, d_Bh);
    cudaGetSymbolAddress((void**)&Bl, d_Bl);
    cudaGetSymbolAddress((void**)&Qh, d_Qh);
    cudaGetSymbolAddress((void**)&Ql, d_Ql);
    cudaGetSymbolAddress((void**)&Kh, d_Kh);
    cudaGetSymbolAddress((void**)&Kl, d_Kl);
    cudaGetSymbolAddress((void**)&Vf, d_Vf);

    cudaFuncSetAttribute(mma_gemm_b, cudaFuncAttributeMaxDynamicSharedMemorySize,
                         GEMM_SMEM);
    cudaFuncSetAttribute(attn_mma_kernel, cudaFuncAttributeMaxDynamicSharedMemorySize,
                         ATTN_SMEM);

    dim3 blk(256);
    dim3 gtile(16, 16);
    dim3 gT(64, 64);

    // operand prep
    split_x<<<T_TOK * HID / (256 * 8), blk>>>(X, Xh, Xl);
    splitT<<<gT, blk>>>(Wq, NQG, WqTh, WqTl);
    splitT<<<gT, blk>>>(Wk, HID, WkTh, WkTl);
    splitT<<<gT, blk>>>(Wv, HID, WvTh, WvTl);
    splitT<<<gT, blk>>>(Wo, HID, WoTh, WoTl);

    // projections
    mma_gemm_b<<<gtile, blk, GEMM_SMEM>>>(Xh, Xl, WqTh, WqTl, qg, HID, NQG);
    gate_gemm<<<T_TOK / 16, blk>>>(X, Wq, qg);
    mma_gemm_b<<<gtile, blk, GEMM_SMEM>>>(Xh, Xl, WkTh, WkTl, kb, HID, HID);
    mma_gemm_b<<<gtile, blk, GEMM_SMEM>>>(Xh, Xl, WvTh, WvTl, vb, HID, HID);

    norm_rope_kernel<<<T_TOK, 256>>>(qg, kb, vb, qw, kw, pos,
                                     Qh, Ql, Kh, Kl, Vf);

    dim3 ga(T_TOK / BR, NH);   // 32 x 16
    attn_mma_kernel<<<ga, 128, ATTN_SMEM>>>(Qh, Ql, Kh, Kl, Vf,
                                            qg, Bh, Bl, pos);

    mma_gemm_b<<<gtile, blk, GEMM_SMEM>>>(Bh, Bl, WoTh, WoTl, out, HID, HID);
}